// round 13
// baseline (speedup 1.0000x reference)
#include <cuda_runtime.h>
#include <cuda_fp16.h>
#include <math.h>
#include <stdint.h>

// ---------------- Problem constants ----------------
#define BATCH 4
#define SEQ   2048
#define T_TOT (BATCH*SEQ)      // 8192
#define D_MODEL 768
#define L_LAYERS 4
#define N_STATE 16
#define K_CONV  4
#define I_INNER 1536           // 2*D_MODEL
#define DT_RANK 48
#define VOCAB 32000
#define EPS 1e-5f

// chunked scan config
#define CH_LEN 128
#define NCHUNK (SEQ / CH_LEN)   // 16

// ---------------- Scratch (static device globals; no allocs) ----------------
__device__ float  g_h   [(size_t)T_TOT * D_MODEL];
__device__ __half g_x   [(size_t)T_TOT * D_MODEL];
__device__ __half g_proj[(size_t)T_TOT * 2 * I_INNER];
__device__ __half g_ut  [(size_t)T_TOT * I_INNER];
__device__ __half g_xdbl[(size_t)T_TOT * 80];
__device__ __half g_dt  [(size_t)T_TOT * I_INNER];
__device__ __half g_y   [(size_t)T_TOT * I_INNER];
__device__ float  g_hn  [BATCH * D_MODEL];
__device__ float  g_xpart[(size_t)4 * T_TOT * 80];
// fp16 weight copies (all layers)
__device__ __half g_wh_in [(size_t)L_LAYERS * 2 * I_INNER * D_MODEL];
__device__ __half g_wh_x  [(size_t)L_LAYERS * 80 * I_INNER];
__device__ __half g_wh_dt [(size_t)L_LAYERS * I_INNER * DT_RANK];
__device__ __half g_wh_out[(size_t)L_LAYERS * D_MODEL * I_INNER];
// chunked-scan state: layout [b][c][i][n]
__device__ float g_pA  [(size_t)BATCH * NCHUNK * I_INNER * N_STATE];
__device__ float g_hf  [(size_t)BATCH * NCHUNK * I_INNER * N_STATE];
__device__ float g_hin [(size_t)BATCH * NCHUNK * I_INNER * N_STATE];

// ---------------- small helpers ----------------
__device__ __forceinline__ uint32_t smem_u32(const void* p) {
    uint32_t a;
    asm("{ .reg .u64 t; cvta.to.shared.u64 t, %1; cvt.u32.u64 %0, t; }"
        : "=r"(a) : "l"(p));
    return a;
}
__device__ __forceinline__ void cp_async16(uint32_t dst, const void* src, int sz) {
    asm volatile("cp.async.cg.shared.global [%0], [%1], 16, %2;"
                 :: "r"(dst), "l"(src), "r"(sz) : "memory");
}
#define CP_COMMIT() asm volatile("cp.async.commit_group;" ::: "memory")
#define CP_WAIT1()  asm volatile("cp.async.wait_group 1;" ::: "memory")

__device__ __forceinline__ void mma_fp16(float* d, uint32_t a0, uint32_t a1,
                                         uint32_t a2, uint32_t a3,
                                         uint32_t b0, uint32_t b1) {
    asm volatile(
        "mma.sync.aligned.m16n8k16.row.col.f32.f16.f16.f32 "
        "{%0,%1,%2,%3}, {%4,%5,%6,%7}, {%8,%9}, {%0,%1,%2,%3};"
        : "+f"(d[0]), "+f"(d[1]), "+f"(d[2]), "+f"(d[3])
        : "r"(a0), "r"(a1), "r"(a2), "r"(a3), "r"(b0), "r"(b1));
}

__device__ __forceinline__ void ldsm_x4(uint32_t& r0, uint32_t& r1,
                                        uint32_t& r2, uint32_t& r3, uint32_t addr) {
    asm volatile("ldmatrix.sync.aligned.m8n8.x4.shared.b16 {%0,%1,%2,%3}, [%4];"
                 : "=r"(r0), "=r"(r1), "=r"(r2), "=r"(r3) : "r"(addr));
}

__device__ __forceinline__ float softplusf(float v) {
    return (v > 20.f) ? v : log1pf(__expf(v));
}

// ---------------- merged f32 -> fp16 weight conversion (one launch) -------
__global__ void f2h4_kernel(const float* __restrict__ s0, __half* __restrict__ d0, int n0,
                            const float* __restrict__ s1, __half* __restrict__ d1, int n1,
                            const float* __restrict__ s2, __half* __restrict__ d2, int n2,
                            const float* __restrict__ s3, __half* __restrict__ d3, int n3) {
    int i = blockIdx.x * 256 + threadIdx.x;
    int stride = gridDim.x * 256;
    for (int j = i; j < n0 / 2; j += stride) {
        float2 v = ((const float2*)s0)[j];
        ((__half2*)d0)[j] = __floats2half2_rn(v.x, v.y);
    }
    for (int j = i; j < n1 / 2; j += stride) {
        float2 v = ((const float2*)s1)[j];
        ((__half2*)d1)[j] = __floats2half2_rn(v.x, v.y);
    }
    for (int j = i; j < n2 / 2; j += stride) {
        float2 v = ((const float2*)s2)[j];
        ((__half2*)d2)[j] = __floats2half2_rn(v.x, v.y);
    }
    for (int j = i; j < n3 / 2; j += stride) {
        float2 v = ((const float2*)s3)[j];
        ((__half2*)d3)[j] = __floats2half2_rn(v.x, v.y);
    }
}

// ================= tensor-core fp16 GEMM (mma.sync m16n8k16 + ldmatrix) =====
// Template on NTILE (128 or 256). Warp layout 4m x (NTILE/64)n, warp tile
// 32x64, K chunks of 64 halves, 3-stage cp.async pipeline, XOR-swizzle.
// NTILE=128: 256 thr, 2 CTAs/SM.  NTILE=256: 512 thr, 1 CTA/SM (same 16
// warps/SM; A/B smem bytes per MMA drop 192 -> 94, crossbar relief).
// EPI: 0 = store f32 (+splitK z-offset), 1 = f32 +=, 2 = softplus->fp16,
//      3 = store fp16.
#define TG_SMEM128 (3 * (16384 + 16384))
#define TG_SMEM256 (3 * (16384 + 32768))

template<int EPI, int NTILE>
__global__ __launch_bounds__(NTILE == 256 ? 512 : 256, NTILE == 256 ? 1 : 2)
void tgemm(const __half* __restrict__ A, int lda,
           const __half* __restrict__ B, int ldb,
           void* __restrict__ Cv, int ldc,
           int N, int K, const float* __restrict__ bias,
           int Kper, size_t czstride) {
    extern __shared__ char smem[];
    constexpr int T = (NTILE == 256) ? 512 : 256;
    constexpr int ASTG = 16384;
    constexpr int BSTG = NTILE * 128;
    const uint32_t sbA = smem_u32(smem);
    const uint32_t sbB = sbA + 3 * ASTG;

    const int tid = threadIdx.x;
    const int wid = tid >> 5, lane = tid & 31;
    const int warp_m = wid & 3, warp_n = wid >> 2;
    const int r4 = lane >> 2, cc = lane & 3;
    const int m0 = blockIdx.y * 128, n0 = blockIdx.x * NTILE;
    const int Nvalid = (N - n0 < NTILE) ? (N - n0) : NTILE;

    const int koff = blockIdx.z * Kper;
    int Kloc = K - koff; if (Kloc > Kper) Kloc = Kper;
    const __half* Arow = A + (size_t)m0 * lda + koff;
    const __half* Brow = B + (size_t)n0 * ldb + koff;

    const int nc = (Kloc + 63) / 64;

    float acc[2][8][4];
    #pragma unroll
    for (int i = 0; i < 2; i++)
        #pragma unroll
        for (int j = 0; j < 8; j++)
            #pragma unroll
            for (int v = 0; v < 4; v++) acc[i][j][v] = 0.f;

    constexpr int APT = 1024 / T;          // A cp.async ops per thread
    constexpr int BPT = NTILE * 8 / T;     // B cp.async ops per thread (=4)

    const int lrow8 = ((lane & 16) >> 1) + (lane & 7);
    const int gsel  = (lane >> 3) & 1;
    uint32_t aoff[2], boff[4];
    #pragma unroll
    for (int am = 0; am < 2; am++) {
        int row = warp_m * 32 + am * 16 + lrow8;
        aoff[am] = (uint32_t)row * 128 + ((uint32_t)((row & 7) ^ gsel) << 4);
    }
    #pragma unroll
    for (int nb = 0; nb < 4; nb++) {
        int row = warp_n * 64 + nb * 16 + lrow8;
        boff[nb] = (uint32_t)row * 128 + ((uint32_t)((row & 7) ^ gsel) << 4);
    }

    #define ISSUE_CHUNK(ch) do {                                            \
        int _st = (ch) % 3;                                                 \
        uint32_t _ab = sbA + _st * ASTG;                                    \
        uint32_t _bb = sbB + _st * BSTG;                                    \
        int _k0c = (ch) * 64;                                               \
        _Pragma("unroll")                                                   \
        for (int _j = 0; _j < APT; _j++) {                                  \
            int _o = tid * APT + _j;                                        \
            int _r = _o >> 3, _g = _o & 7;                                  \
            int _k0 = _k0c + _g * 8;                                        \
            int _sz = (Kloc - _k0) * 2;                                     \
            _sz = _sz < 0 ? 0 : (_sz > 16 ? 16 : _sz);                      \
            uint32_t _sw = (uint32_t)_r * 128 + ((uint32_t)(_g ^ (_r & 7)) << 4); \
            const __half* _sa = Arow + (size_t)_r * lda + (_sz ? _k0 : 0);  \
            cp_async16(_ab + _sw, _sa, _sz);                                \
        }                                                                   \
        _Pragma("unroll")                                                   \
        for (int _j = 0; _j < BPT; _j++) {                                  \
            int _o = tid * BPT + _j;                                        \
            int _r = _o >> 3, _g = _o & 7;                                  \
            int _k0 = _k0c + _g * 8;                                        \
            int _sz = (Kloc - _k0) * 2;                                     \
            _sz = _sz < 0 ? 0 : (_sz > 16 ? 16 : _sz);                      \
            if (_r >= Nvalid) _sz = 0;                                      \
            uint32_t _sw = (uint32_t)_r * 128 + ((uint32_t)(_g ^ (_r & 7)) << 4); \
            const __half* _sb = Brow + (_sz ? ((size_t)_r * ldb + _k0) : 0); \
            cp_async16(_bb + _sw, _sb, _sz);                                \
        }                                                                   \
    } while (0)

    ISSUE_CHUNK(0);
    CP_COMMIT();
    if (nc > 1) ISSUE_CHUNK(1);
    CP_COMMIT();

    for (int c = 0; c < nc; c++) {
        CP_WAIT1();
        __syncthreads();
        if (c + 2 < nc) ISSUE_CHUNK(c + 2);
        CP_COMMIT();

        const uint32_t pa = sbA + (c % 3) * ASTG;
        const uint32_t pb = sbB + (c % 3) * BSTG;
        const uint32_t Pa0 = pa + aoff[0], Pa1 = pa + aoff[1];
        const uint32_t Pb0 = pb + boff[0], Pb1 = pb + boff[1];
        const uint32_t Pb2 = pb + boff[2], Pb3 = pb + boff[3];

        #pragma unroll
        for (int ks = 0; ks < 4; ks++) {
            const uint32_t xm = (uint32_t)ks << 5;
            uint32_t a00, a01, a02, a03, a10, a11, a12, a13;
            uint32_t b[16];
            ldsm_x4(a00, a01, a02, a03, Pa0 ^ xm);
            ldsm_x4(a10, a11, a12, a13, Pa1 ^ xm);
            ldsm_x4(b[0],  b[1],  b[2],  b[3],  Pb0 ^ xm);
            ldsm_x4(b[4],  b[5],  b[6],  b[7],  Pb1 ^ xm);
            ldsm_x4(b[8],  b[9],  b[10], b[11], Pb2 ^ xm);
            ldsm_x4(b[12], b[13], b[14], b[15], Pb3 ^ xm);
            #pragma unroll
            for (int q = 0; q < 4; q++) {
                mma_fp16(acc[0][2*q+0], a00, a02, a01, a03, b[4*q+0], b[4*q+1]);
                mma_fp16(acc[0][2*q+1], a00, a02, a01, a03, b[4*q+2], b[4*q+3]);
                mma_fp16(acc[1][2*q+0], a10, a12, a11, a13, b[4*q+0], b[4*q+1]);
                mma_fp16(acc[1][2*q+1], a10, a12, a11, a13, b[4*q+2], b[4*q+3]);
            }
        }
    }

    #pragma unroll
    for (int am = 0; am < 2; am++) {
        #pragma unroll
        for (int p = 0; p < 2; p++) {
            int row = m0 + warp_m * 32 + am * 16 + p * 8 + r4;
            #pragma unroll
            for (int an = 0; an < 8; an++) {
                int col = n0 + warp_n * 64 + an * 8 + cc * 2;
                if (col < N) {
                    float vx = acc[am][an][2 * p], vy = acc[am][an][2 * p + 1];
                    if (EPI == 0) {
                        float* cp = (float*)Cv + (size_t)blockIdx.z * czstride
                                  + (size_t)row * ldc + col;
                        *(float2*)cp = make_float2(vx, vy);
                    } else if (EPI == 1) {
                        float* cp = (float*)Cv + (size_t)row * ldc + col;
                        float2 o = *(float2*)cp;
                        *(float2*)cp = make_float2(vx + o.x, vy + o.y);
                    } else if (EPI == 2) {
                        float2 bb2 = *(const float2*)(bias + col);
                        __half* cp = (__half*)Cv + (size_t)row * ldc + col;
                        *(__half2*)cp = __floats2half2_rn(
                            softplusf(vx + bb2.x), softplusf(vy + bb2.y));
                    } else {  // EPI == 3
                        __half* cp = (__half*)Cv + (size_t)row * ldc + col;
                        *(__half2*)cp = __floats2half2_rn(vx, vy);
                    }
                }
            }
        }
    }
    #undef ISSUE_CHUNK
}

// ---------------- split-K combine (4 f32 partials -> fp16 out) ------------
__global__ void combine4_kernel(const float* __restrict__ part,
                                __half* __restrict__ out, int n) {
    int i = blockIdx.x * 256 + threadIdx.x;
    if (i < n) {
        float s = part[i] + part[(size_t)n + i] + part[2 * (size_t)n + i]
                + part[3 * (size_t)n + i];
        out[i] = __float2half_rn(s);
    }
}

// ---------------- Embedding gather ----------------
__global__ void gather_kernel(const int* __restrict__ ids,
                              const float* __restrict__ embed,
                              float* __restrict__ h) {
    int t = blockIdx.x;
    int c = threadIdx.x;
    int id = ids[t];
    const float4* src = (const float4*)(embed + (size_t)id * D_MODEL);
    float4* dst = (float4*)(h + (size_t)t * D_MODEL);
    dst[c] = src[c];
}

// ---------------- RMSNorm (192 threads, float4); 0 = f32 out, 1 = fp16 ---
__global__ void rmsnorm_kernel(const float* __restrict__ x, long in_stride,
                               const float* __restrict__ w,
                               void* __restrict__ yv, long out_stride,
                               int half_out) {
    long r = blockIdx.x;
    const float* xr = x + r * in_stride;
    int tid = threadIdx.x; // 192
    float4 v = ((const float4*)xr)[tid];
    float s = v.x * v.x + v.y * v.y + v.z * v.z + v.w * v.w;
    #pragma unroll
    for (int o = 16; o; o >>= 1) s += __shfl_xor_sync(0xffffffffu, s, o);
    __shared__ float ws[6];
    __shared__ float sc;
    if ((tid & 31) == 0) ws[tid >> 5] = s;
    __syncthreads();
    if (tid == 0) {
        float tsum = 0.f;
        #pragma unroll
        for (int k = 0; k < 6; k++) tsum += ws[k];
        sc = rsqrtf(tsum * (1.0f / D_MODEL) + EPS);
    }
    __syncthreads();
    float scale = sc;
    float4 wv = ((const float4*)w)[tid];
    float o0 = v.x * scale * wv.x;
    float o1 = v.y * scale * wv.y;
    float o2 = v.z * scale * wv.z;
    float o3 = v.w * scale * wv.w;
    if (half_out) {
        __half2* yr = (__half2*)((__half*)yv + r * out_stride);
        yr[2 * tid]     = __floats2half2_rn(o0, o1);
        yr[2 * tid + 1] = __floats2half2_rn(o2, o3);
    } else {
        float4* yr = (float4*)((float*)yv + r * out_stride);
        yr[tid] = make_float4(o0, o1, o2, o3);
    }
}

// ---------------- Depthwise causal conv + bias + SiLU (half2, 2ch x 4t) ---
__global__ void conv_silu_kernel(const __half* __restrict__ proj,
                                 const float* __restrict__ cw,
                                 const float* __restrict__ cb,
                                 __half* __restrict__ ut) {
    long idx = (long)blockIdx.x * 256 + threadIdx.x;
    if (idx >= (long)(T_TOT / 4) * (I_INNER / 2)) return;
    int i2 = (int)(idx % (I_INNER / 2));
    long tq = idx / (I_INNER / 2);
    long t0 = tq * 4;
    int tl0 = (int)(t0 & (SEQ - 1));
    const __half2* p2 = (const __half2*)proj;
    const long S2 = I_INNER;
    long base = t0 * S2 + i2;

    float4 wa = ((const float4*)cw)[2 * i2];
    float4 wb = ((const float4*)cw)[2 * i2 + 1];
    float2 bia = ((const float2*)cb)[i2];

    float2 v[7];
    if (tl0 == 0) {
        v[0] = make_float2(0.f, 0.f); v[1] = v[0]; v[2] = v[0];
    } else {
        v[0] = __half22float2(p2[base - 3 * S2]);
        v[1] = __half22float2(p2[base - 2 * S2]);
        v[2] = __half22float2(p2[base - 1 * S2]);
    }
    v[3] = __half22float2(p2[base]);
    v[4] = __half22float2(p2[base + 1 * S2]);
    v[5] = __half22float2(p2[base + 2 * S2]);
    v[6] = __half22float2(p2[base + 3 * S2]);

    __half2* up = (__half2*)ut + t0 * (I_INNER / 2) + i2;
    #pragma unroll
    for (int k = 0; k < 4; k++) {
        float sa = bia.x, sb = bia.y;
        sa = fmaf(wa.x, v[k].x, sa);     sb = fmaf(wb.x, v[k].y, sb);
        sa = fmaf(wa.y, v[k + 1].x, sa); sb = fmaf(wb.y, v[k + 1].y, sb);
        sa = fmaf(wa.z, v[k + 2].x, sa); sb = fmaf(wb.z, v[k + 2].y, sb);
        sa = fmaf(wa.w, v[k + 3].x, sa); sb = fmaf(wb.w, v[k + 3].y, sb);
        float siga = 1.f / (1.f + __expf(-sa));
        float sigb = 1.f / (1.f + __expf(-sb));
        up[(size_t)k * (I_INNER / 2)] = __floats2half2_rn(sa * siga, sb * sigb);
    }
}

// ================= Chunked selective scan =================
__device__ __forceinline__ int a_is_arith(const float* A) {
    int ok = 1;
    #pragma unroll
    for (int n = 1; n < N_STATE; n++) {
        float ref = (float)(n + 1) * A[0];
        ok &= (fabsf(A[n] - ref) <= 1e-4f * fabsf(ref));
    }
    return ok;
}

__global__ __launch_bounds__(128)
void scan_phase1(const __half* __restrict__ dt,
                 const __half* __restrict__ ut,
                 const __half* __restrict__ xdbl,
                 const float* __restrict__ A_log,
                 float* __restrict__ pA_out,
                 float* __restrict__ hf_out) {
    int i = blockIdx.x * 128 + threadIdx.x;
    int c = blockIdx.y;
    int b = blockIdx.z;
    float A[N_STATE], h[N_STATE], pA[N_STATE];
    #pragma unroll
    for (int n = 0; n < N_STATE; n++) {
        A[n] = -__expf(A_log[i * N_STATE + n]);
        h[n] = 0.f; pA[n] = 1.f;
    }
    const int fast = a_is_arith(A);
    const float A0 = A[0];
    int t0 = c * CH_LEN;
    const __half* dtp = dt + (size_t)(b * SEQ + t0) * I_INNER + i;
    const __half* up  = ut + (size_t)(b * SEQ + t0) * I_INNER + i;
    const __half* xp  = xdbl + (size_t)(b * SEQ + t0) * 80;
    if (fast) {
        for (int t = 0; t < CH_LEN; t += 2) {
            float d0 = __half2float(dtp[(size_t)t * I_INNER]);
            float u0 = __half2float(up[(size_t)t * I_INNER]);
            float d1 = __half2float(dtp[(size_t)(t + 1) * I_INNER]);
            float u1 = __half2float(up[(size_t)(t + 1) * I_INNER]);
            float du0 = d0 * u0, du1 = d1 * u1;
            const __half2* xr0 = (const __half2*)(xp + (size_t)t * 80 + 48);
            const __half2* xr1 = (const __half2*)(xp + (size_t)(t + 1) * 80 + 48);
            float B0[N_STATE], B1[N_STATE];
            #pragma unroll
            for (int m = 0; m < 8; m++) {
                float2 b0 = __half22float2(xr0[m]);
                float2 b1 = __half22float2(xr1[m]);
                B0[2*m] = b0.x; B0[2*m+1] = b0.y;
                B1[2*m] = b1.x; B1[2*m+1] = b1.y;
            }
            float q0 = __expf(d0 * A0), q1 = __expf(d1 * A0);
            float c0 = 1.f, c1 = 1.f;
            #pragma unroll
            for (int n = 0; n < N_STATE; n++) {
                c0 *= q0; c1 *= q1;
                h[n] = fmaf(c0, h[n], du0 * B0[n]);
                h[n] = fmaf(c1, h[n], du1 * B1[n]);
                pA[n] *= c0 * c1;
            }
        }
    } else {
        for (int t = 0; t < CH_LEN; t++) {
            float d = __half2float(dtp[(size_t)t * I_INNER]);
            float u = __half2float(up[(size_t)t * I_INNER]);
            float du = d * u;
            const __half* xr = xp + (size_t)t * 80;
            #pragma unroll
            for (int n = 0; n < N_STATE; n++) {
                float Bn = __half2float(xr[48 + n]);
                float dA = __expf(d * A[n]);
                pA[n] *= dA;
                h[n] = fmaf(dA, h[n], du * Bn);
            }
        }
    }
    size_t off = (size_t)((b * NCHUNK + c) * I_INNER + i) * N_STATE;
    #pragma unroll
    for (int n = 0; n < N_STATE; n++) {
        pA_out[off + n] = pA[n];
        hf_out[off + n] = h[n];
    }
}

__global__ void scan_phase2(const float* __restrict__ pA,
                            const float* __restrict__ hf,
                            float* __restrict__ hin) {
    int ch = blockIdx.x * 128 + threadIdx.x;
    if (ch >= BATCH * I_INNER) return;
    int b = ch / I_INNER, i = ch % I_INNER;
    float h[N_STATE];
    #pragma unroll
    for (int n = 0; n < N_STATE; n++) h[n] = 0.f;
    for (int c = 0; c < NCHUNK; c++) {
        size_t off = (size_t)((b * NCHUNK + c) * I_INNER + i) * N_STATE;
        #pragma unroll
        for (int q = 0; q < 4; q++) {
            float4 p4 = *(const float4*)(pA + off + 4 * q);
            float4 f4 = *(const float4*)(hf + off + 4 * q);
            *(float4*)(hin + off + 4 * q) =
                make_float4(h[4*q], h[4*q+1], h[4*q+2], h[4*q+3]);
            h[4*q]   = fmaf(p4.x, h[4*q],   f4.x);
            h[4*q+1] = fmaf(p4.y, h[4*q+1], f4.y);
            h[4*q+2] = fmaf(p4.z, h[4*q+2], f4.z);
            h[4*q+3] = fmaf(p4.w, h[4*q+3], f4.w);
        }
    }
}

__global__ __launch_bounds__(128)
void scan_phase3(const __half* __restrict__ dt,
                 const __half* __restrict__ ut,
                 const __half* __restrict__ xdbl,
                 const float* __restrict__ A_log,
                 const float* __restrict__ Dp,
                 const __half* __restrict__ proj,
                 const float* __restrict__ hin,
                 __half* __restrict__ y) {
    int i = blockIdx.x * 128 + threadIdx.x;
    int c = blockIdx.y;
    int b = blockIdx.z;
    float A[N_STATE], h[N_STATE];
    size_t soff = (size_t)((b * NCHUNK + c) * I_INNER + i) * N_STATE;
    #pragma unroll
    for (int n = 0; n < N_STATE; n++) {
        A[n] = -__expf(A_log[i * N_STATE + n]);
        h[n] = hin[soff + n];
    }
    const int fast = a_is_arith(A);
    const float A0 = A[0];
    float Di = Dp[i];
    int t0 = c * CH_LEN;
    const __half* dtp = dt + (size_t)(b * SEQ + t0) * I_INNER + i;
    const __half* up  = ut + (size_t)(b * SEQ + t0) * I_INNER + i;
    const __half* gp  = proj + (size_t)(b * SEQ + t0) * 2 * I_INNER + I_INNER + i;
    const __half* xp  = xdbl + (size_t)(b * SEQ + t0) * 80;
    __half* yp        = y + (size_t)(b * SEQ + t0) * I_INNER + i;
    if (fast) {
        for (int t = 0; t < CH_LEN; t++) {
            float d = __half2float(dtp[(size_t)t * I_INNER]);
            float u = __half2float(up[(size_t)t * I_INNER]);
            float g = __half2float(gp[(size_t)t * 2 * I_INNER]);
            float du = d * u;
            const __half2* xr2 = (const __half2*)(xp + (size_t)t * 80 + 48);
            float Bn[N_STATE], Cn[N_STATE];
            #pragma unroll
            for (int m = 0; m < 8; m++) {
                float2 bb = __half22float2(xr2[m]);
                float2 cx = __half22float2(xr2[8 + m]);
                Bn[2*m] = bb.x; Bn[2*m+1] = bb.y;
                Cn[2*m] = cx.x; Cn[2*m+1] = cx.y;
            }
            float q = __expf(d * A0);
            float dAc = 1.f;
            float acc = 0.f;
            #pragma unroll
            for (int n = 0; n < N_STATE; n++) {
                dAc *= q;
                h[n] = fmaf(dAc, h[n], du * Bn[n]);
                acc = fmaf(h[n], Cn[n], acc);
            }
            float sig = 1.f / (1.f + __expf(-g));
            yp[(size_t)t * I_INNER] = __float2half_rn((acc + u * Di) * (g * sig));
        }
    } else {
        for (int t = 0; t < CH_LEN; t++) {
            float d = __half2float(dtp[(size_t)t * I_INNER]);
            float u = __half2float(up[(size_t)t * I_INNER]);
            float du = d * u;
            const __half* xr = xp + (size_t)t * 80;
            float acc = 0.f;
            #pragma unroll
            for (int n = 0; n < N_STATE; n++) {
                float Bn = __half2float(xr[48 + n]);
                float Cx = __half2float(xr[64 + n]);
                float dA = __expf(d * A[n]);
                h[n] = fmaf(dA, h[n], du * Bn);
                acc = fmaf(h[n], Cx, acc);
            }
            float g = __half2float(gp[(size_t)t * 2 * I_INNER]);
            float sig = 1.f / (1.f + __expf(-g));
            yp[(size_t)t * I_INNER] = __float2half_rn((acc + u * Di) * (g * sig));
        }
    }
}

// ---------------- Logits: out[b,v] = dot(hn[b], embed[v]) ----------------
__global__ void logits_kernel(const float* __restrict__ hn,
                              const float* __restrict__ embed,
                              float* __restrict__ out) {
    __shared__ float sh[BATCH * D_MODEL];
    int tid = threadIdx.x; // 256
    for (int j = tid; j < BATCH * D_MODEL; j += 256) sh[j] = hn[j];
    __syncthreads();
    int warp = tid >> 5, lane = tid & 31;
    int v = blockIdx.x * 8 + warp;
    if (v >= VOCAB) return;
    const float* e = embed + (size_t)v * D_MODEL;
    float a0 = 0.f, a1 = 0.f, a2 = 0.f, a3 = 0.f;
    for (int j = lane; j < D_MODEL; j += 32) {
        float ev = e[j];
        a0 = fmaf(ev, sh[j], a0);
        a1 = fmaf(ev, sh[D_MODEL + j], a1);
        a2 = fmaf(ev, sh[2 * D_MODEL + j], a2);
        a3 = fmaf(ev, sh[3 * D_MODEL + j], a3);
    }
    #pragma unroll
    for (int o = 16; o; o >>= 1) {
        a0 += __shfl_down_sync(0xffffffffu, a0, o);
        a1 += __shfl_down_sync(0xffffffffu, a1, o);
        a2 += __shfl_down_sync(0xffffffffu, a2, o);
        a3 += __shfl_down_sync(0xffffffffu, a3, o);
    }
    if (lane == 0) {
        out[(size_t)0 * VOCAB + v] = a0;
        out[(size_t)1 * VOCAB + v] = a1;
        out[(size_t)2 * VOCAB + v] = a2;
        out[(size_t)3 * VOCAB + v] = a3;
    }
}

// ---------------- Launch ----------------
extern "C" void kernel_launch(void* const* d_in, const int* in_sizes, int n_in,
                              void* d_out, int out_size) {
    const int*   ids       = (const int*)  d_in[0];
    const float* embed     = (const float*)d_in[1];
    const float* norm_w    = (const float*)d_in[2];
    const float* in_proj_w = (const float*)d_in[3];
    const float* conv_w    = (const float*)d_in[4];
    const float* conv_b    = (const float*)d_in[5];
    const float* x_proj_w  = (const float*)d_in[6];
    const float* dt_proj_w = (const float*)d_in[7];
    const float* dt_proj_b = (const float*)d_in[8];
    const float* A_log     = (const float*)d_in[9];
    const float* D_param   = (const float*)d_in[10];
    const float* out_proj_w= (const float*)d_in[11];
    const float* norm_f_w  = (const float*)d_in[12];
    float* out = (float*)d_out;

    float *h, *hn, *pA, *hf, *hin, *xpart;
    __half *x, *proj, *ut, *xdbl, *dt, *y, *wh_in, *wh_x, *wh_dt, *wh_out;
    cudaGetSymbolAddress((void**)&h,     g_h);
    cudaGetSymbolAddress((void**)&x,     g_x);
    cudaGetSymbolAddress((void**)&proj,  g_proj);
    cudaGetSymbolAddress((void**)&ut,    g_ut);
    cudaGetSymbolAddress((void**)&xdbl,  g_xdbl);
    cudaGetSymbolAddress((void**)&dt,    g_dt);
    cudaGetSymbolAddress((void**)&y,     g_y);
    cudaGetSymbolAddress((void**)&hn,    g_hn);
    cudaGetSymbolAddress((void**)&pA,    g_pA);
    cudaGetSymbolAddress((void**)&hf,    g_hf);
    cudaGetSymbolAddress((void**)&hin,   g_hin);
    cudaGetSymbolAddress((void**)&xpart, g_xpart);
    cudaGetSymbolAddress((void**)&wh_in, g_wh_in);
    cudaGetSymbolAddress((void**)&wh_x,  g_wh_x);
    cudaGetSymbolAddress((void**)&wh_dt, g_wh_dt);
    cudaGetSymbolAddress((void**)&wh_out,g_wh_out);

    cudaFuncSetAttribute(tgemm<3,256>, cudaFuncAttributeMaxDynamicSharedMemorySize, TG_SMEM256);
    cudaFuncSetAttribute(tgemm<1,256>, cudaFuncAttributeMaxDynamicSharedMemorySize, TG_SMEM256);
    cudaFuncSetAttribute(tgemm<0,128>, cudaFuncAttributeMaxDynamicSharedMemorySize, TG_SMEM128);
    cudaFuncSetAttribute(tgemm<2,128>, cudaFuncAttributeMaxDynamicSharedMemorySize, TG_SMEM128);

    // weight conversions (all layers, one launch)
    {
        int n1 = L_LAYERS * 2 * I_INNER * D_MODEL;
        int n2 = L_LAYERS * 80 * I_INNER;
        int n3 = L_LAYERS * I_INNER * DT_RANK;
        int n4 = L_LAYERS * D_MODEL * I_INNER;
        f2h4_kernel<<<(n1 / 2 + 255) / 256, 256>>>(
            in_proj_w, wh_in, n1, x_proj_w, wh_x, n2,
            dt_proj_w, wh_dt, n3, out_proj_w, wh_out, n4);
    }

    gather_kernel<<<T_TOT, 192>>>(ids, embed, h);

    const int NXD = T_TOT * 80;

    for (int l = 0; l < L_LAYERS; l++) {
        rmsnorm_kernel<<<T_TOT, 192>>>(h, D_MODEL, norm_w + l * D_MODEL, x, D_MODEL, 1);

        // proj = x @ in_proj_w^T   (8192 x 3072 x 768), NTILE=256, fp16 out
        tgemm<3,256><<<dim3(12, 64), 512, TG_SMEM256>>>(
            x, D_MODEL, wh_in + (size_t)l * 2 * I_INNER * D_MODEL, D_MODEL,
            proj, 2 * I_INNER, 2 * I_INNER, D_MODEL, nullptr, D_MODEL, 0);

        conv_silu_kernel<<<((T_TOT / 4) * (I_INNER / 2) + 255) / 256, 256>>>(
            proj, conv_w + (size_t)l * I_INNER * K_CONV, conv_b + (size_t)l * I_INNER, ut);

        // xdbl = ut @ x_proj_w^T   (8192 x 80 x 1536), split-K x4 + combine
        tgemm<0,128><<<dim3(1, 64, 4), 256, TG_SMEM128>>>(
            ut, I_INNER, wh_x + (size_t)l * 80 * I_INNER, I_INNER,
            xpart, 80, 80, I_INNER, nullptr, 384, (size_t)NXD);
        combine4_kernel<<<(NXD + 255) / 256, 256>>>(xpart, xdbl, NXD);

        // dt = softplus(dt_r @ dt_proj_w^T + b)   (8192 x 1536 x 48), fp16 out
        tgemm<2,128><<<dim3(12, 64), 256, TG_SMEM128>>>(
            xdbl, 80, wh_dt + (size_t)l * I_INNER * DT_RANK, DT_RANK,
            dt, I_INNER, I_INNER, DT_RANK, dt_proj_b + (size_t)l * I_INNER,
            DT_RANK, 0);

        // chunked parallel scan
        const float* Al = A_log + (size_t)l * I_INNER * N_STATE;
        scan_phase1<<<dim3(I_INNER / 128, NCHUNK, BATCH), 128>>>(
            dt, ut, xdbl, Al, pA, hf);
        scan_phase2<<<(BATCH * I_INNER + 127) / 128, 128>>>(pA, hf, hin);
        scan_phase3<<<dim3(I_INNER / 128, NCHUNK, BATCH), 128>>>(
            dt, ut, xdbl, Al, D_param + (size_t)l * I_INNER, proj, hin, y);

        // h += y @ out_proj_w^T    (8192 x 768 x 1536), NTILE=256
        tgemm<1,256><<<dim3(3, 64), 512, TG_SMEM256>>>(
            y, I_INNER, wh_out + (size_t)l * D_MODEL * I_INNER, I_INNER,
            h, D_MODEL, D_MODEL, I_INNER, nullptr, I_INNER, 0);
    }

    rmsnorm_kernel<<<BATCH, 192>>>(h + (size_t)(SEQ - 1) * D_MODEL,
                                   (long)SEQ * D_MODEL, norm_f_w, hn, D_MODEL, 0);
    logits_kernel<<<(VOCAB + 7) / 8, 256>>>(hn, embed, out);
}

// round 14
// speedup vs baseline: 1.6637x; 1.6637x over previous
#include <cuda_runtime.h>
#include <cuda_fp16.h>
#include <math.h>
#include <stdint.h>

// ---------------- Problem constants ----------------
#define BATCH 4
#define SEQ   2048
#define T_TOT (BATCH*SEQ)      // 8192
#define D_MODEL 768
#define L_LAYERS 4
#define N_STATE 16
#define K_CONV  4
#define I_INNER 1536           // 2*D_MODEL
#define DT_RANK 48
#define VOCAB 32000
#define EPS 1e-5f

// chunked scan config
#define CH_LEN 128
#define NCHUNK (SEQ / CH_LEN)   // 16

// ---------------- Scratch (static device globals; no allocs) ----------------
__device__ float  g_h   [(size_t)T_TOT * D_MODEL];
__device__ __half g_x   [(size_t)T_TOT * D_MODEL];
__device__ __half g_proj[(size_t)T_TOT * 2 * I_INNER];
__device__ __half g_ut  [(size_t)T_TOT * I_INNER];
__device__ __half g_xdbl[(size_t)T_TOT * 80];
__device__ __half g_dt  [(size_t)T_TOT * I_INNER];
__device__ __half g_y   [(size_t)T_TOT * I_INNER];
__device__ float  g_hn  [BATCH * D_MODEL];
__device__ float  g_xpart[(size_t)4 * T_TOT * 80];
// fp16 weight copies (all layers)
__device__ __half g_wh_in [(size_t)L_LAYERS * 2 * I_INNER * D_MODEL];
__device__ __half g_wh_x  [(size_t)L_LAYERS * 80 * I_INNER];
__device__ __half g_wh_dt [(size_t)L_LAYERS * I_INNER * DT_RANK];
__device__ __half g_wh_out[(size_t)L_LAYERS * D_MODEL * I_INNER];
// chunked-scan state: layout [b][c][i][n]
__device__ float g_pA  [(size_t)BATCH * NCHUNK * I_INNER * N_STATE];
__device__ float g_hf  [(size_t)BATCH * NCHUNK * I_INNER * N_STATE];
__device__ float g_hin [(size_t)BATCH * NCHUNK * I_INNER * N_STATE];

// ---------------- small helpers ----------------
__device__ __forceinline__ uint32_t smem_u32(const void* p) {
    uint32_t a;
    asm("{ .reg .u64 t; cvta.to.shared.u64 t, %1; cvt.u32.u64 %0, t; }"
        : "=r"(a) : "l"(p));
    return a;
}
__device__ __forceinline__ void cp_async16(uint32_t dst, const void* src, int sz) {
    asm volatile("cp.async.cg.shared.global [%0], [%1], 16, %2;"
                 :: "r"(dst), "l"(src), "r"(sz) : "memory");
}
#define CP_COMMIT() asm volatile("cp.async.commit_group;" ::: "memory")
#define CP_WAIT1()  asm volatile("cp.async.wait_group 1;" ::: "memory")

__device__ __forceinline__ void mma_fp16(float* d, uint32_t a0, uint32_t a1,
                                         uint32_t a2, uint32_t a3,
                                         uint32_t b0, uint32_t b1) {
    asm volatile(
        "mma.sync.aligned.m16n8k16.row.col.f32.f16.f16.f32 "
        "{%0,%1,%2,%3}, {%4,%5,%6,%7}, {%8,%9}, {%0,%1,%2,%3};"
        : "+f"(d[0]), "+f"(d[1]), "+f"(d[2]), "+f"(d[3])
        : "r"(a0), "r"(a1), "r"(a2), "r"(a3), "r"(b0), "r"(b1));
}

__device__ __forceinline__ void ldsm_x4(uint32_t& r0, uint32_t& r1,
                                        uint32_t& r2, uint32_t& r3, uint32_t addr) {
    asm volatile("ldmatrix.sync.aligned.m8n8.x4.shared.b16 {%0,%1,%2,%3}, [%4];"
                 : "=r"(r0), "=r"(r1), "=r"(r2), "=r"(r3) : "r"(addr));
}

__device__ __forceinline__ float softplusf(float v) {
    return (v > 20.f) ? v : log1pf(__expf(v));
}

// ---------------- merged f32 -> fp16 weight conversion (one launch) -------
__global__ void f2h4_kernel(const float* __restrict__ s0, __half* __restrict__ d0, int n0,
                            const float* __restrict__ s1, __half* __restrict__ d1, int n1,
                            const float* __restrict__ s2, __half* __restrict__ d2, int n2,
                            const float* __restrict__ s3, __half* __restrict__ d3, int n3) {
    int i = blockIdx.x * 256 + threadIdx.x;
    int stride = gridDim.x * 256;
    for (int j = i; j < n0 / 2; j += stride) {
        float2 v = ((const float2*)s0)[j];
        ((__half2*)d0)[j] = __floats2half2_rn(v.x, v.y);
    }
    for (int j = i; j < n1 / 2; j += stride) {
        float2 v = ((const float2*)s1)[j];
        ((__half2*)d1)[j] = __floats2half2_rn(v.x, v.y);
    }
    for (int j = i; j < n2 / 2; j += stride) {
        float2 v = ((const float2*)s2)[j];
        ((__half2*)d2)[j] = __floats2half2_rn(v.x, v.y);
    }
    for (int j = i; j < n3 / 2; j += stride) {
        float2 v = ((const float2*)s3)[j];
        ((__half2*)d3)[j] = __floats2half2_rn(v.x, v.y);
    }
}

// ================= tensor-core fp16 GEMM (R12 config: 128x128, 8 warps) =====
// C[m,n] = sum_k A[m,k]*B[n,k].  A: 8192 x K rm fp16, B: N x K rm fp16.
// CTA tile 128x128, 8 warps (4m x 2n), warp tile 32x64, K chunks of 64 halves,
// 3-stage cp.async pipeline w/ single sync, XOR-swizzled smem, batched ldsm.
// 2 CTAs/SM (hard requirement: sync bubbles need a co-resident CTA).
// EPI: 0 = store f32 (+splitK z-offset), 1 = f32 +=, 2 = softplus->fp16,
//      3 = store fp16.
#define TG_SMEM (6 * 16384)

template<int EPI>
__global__ __launch_bounds__(256, 2)
void tgemm(const __half* __restrict__ A, int lda,
           const __half* __restrict__ B, int ldb,
           void* __restrict__ Cv, int ldc,
           int N, int K, const float* __restrict__ bias,
           int Kper, size_t czstride) {
    extern __shared__ char smem[];
    const uint32_t sbA = smem_u32(smem);
    const uint32_t sbB = sbA + 3 * 16384;

    const int tid = threadIdx.x;
    const int wid = tid >> 5, lane = tid & 31;
    const int warp_m = wid >> 1, warp_n = wid & 1;
    const int r4 = lane >> 2, cc = lane & 3;
    const int m0 = blockIdx.y * 128, n0 = blockIdx.x * 128;
    const int Nvalid = (N - n0 < 128) ? (N - n0) : 128;

    const int koff = blockIdx.z * Kper;
    int Kloc = K - koff; if (Kloc > Kper) Kloc = Kper;
    const __half* Arow = A + (size_t)m0 * lda + koff;
    const __half* Brow = B + (size_t)n0 * ldb + koff;

    const int nc = (Kloc + 63) / 64;

    float acc[2][8][4];
    #pragma unroll
    for (int i = 0; i < 2; i++)
        #pragma unroll
        for (int j = 0; j < 8; j++)
            #pragma unroll
            for (int v = 0; v < 4; v++) acc[i][j][v] = 0.f;

    const int crow = tid >> 1;
    const int gb = (tid & 1) * 4;
    const bool bvalid = crow < Nvalid;
    const uint32_t swbase = (uint32_t)crow * 128;

    const int lrow8 = ((lane & 16) >> 1) + (lane & 7);
    const int gsel  = (lane >> 3) & 1;
    uint32_t aoff[2], boff[4];
    #pragma unroll
    for (int am = 0; am < 2; am++) {
        int row = warp_m * 32 + am * 16 + lrow8;
        aoff[am] = (uint32_t)row * 128 + ((uint32_t)((row & 7) ^ gsel) << 4);
    }
    #pragma unroll
    for (int nb = 0; nb < 4; nb++) {
        int row = warp_n * 64 + nb * 16 + lrow8;
        boff[nb] = (uint32_t)row * 128 + ((uint32_t)((row & 7) ^ gsel) << 4);
    }

    #define ISSUE_CHUNK(ch) do {                                            \
        int _st = (ch) % 3;                                                 \
        uint32_t _ab = sbA + _st * 16384;                                   \
        uint32_t _bb = sbB + _st * 16384;                                   \
        int _k0c = (ch) * 64;                                               \
        _Pragma("unroll")                                                   \
        for (int _j = 0; _j < 4; _j++) {                                    \
            int _g = gb + _j;                                               \
            int _k0 = _k0c + _g * 8;                                        \
            int _sz = (Kloc - _k0) * 2;                                     \
            _sz = _sz < 0 ? 0 : (_sz > 16 ? 16 : _sz);                      \
            uint32_t _sw = swbase + ((uint32_t)(_g ^ (crow & 7)) << 4);     \
            const __half* _sa = Arow + (size_t)crow * lda + (_sz ? _k0 : 0); \
            cp_async16(_ab + _sw, _sa, _sz);                                \
            int _szb = bvalid ? _sz : 0;                                    \
            const __half* _sb = Brow + (_szb ? ((size_t)crow * ldb + _k0) : 0); \
            cp_async16(_bb + _sw, _sb, _szb);                               \
        }                                                                   \
    } while (0)

    ISSUE_CHUNK(0);
    CP_COMMIT();
    if (nc > 1) ISSUE_CHUNK(1);
    CP_COMMIT();

    for (int c = 0; c < nc; c++) {
        CP_WAIT1();
        __syncthreads();
        if (c + 2 < nc) ISSUE_CHUNK(c + 2);
        CP_COMMIT();

        const uint32_t pa = sbA + (c % 3) * 16384;
        const uint32_t pb = sbB + (c % 3) * 16384;
        const uint32_t Pa0 = pa + aoff[0], Pa1 = pa + aoff[1];
        const uint32_t Pb0 = pb + boff[0], Pb1 = pb + boff[1];
        const uint32_t Pb2 = pb + boff[2], Pb3 = pb + boff[3];

        #pragma unroll
        for (int ks = 0; ks < 4; ks++) {
            const uint32_t xm = (uint32_t)ks << 5;
            uint32_t a00, a01, a02, a03, a10, a11, a12, a13;
            uint32_t b[16];
            ldsm_x4(a00, a01, a02, a03, Pa0 ^ xm);
            ldsm_x4(a10, a11, a12, a13, Pa1 ^ xm);
            ldsm_x4(b[0],  b[1],  b[2],  b[3],  Pb0 ^ xm);
            ldsm_x4(b[4],  b[5],  b[6],  b[7],  Pb1 ^ xm);
            ldsm_x4(b[8],  b[9],  b[10], b[11], Pb2 ^ xm);
            ldsm_x4(b[12], b[13], b[14], b[15], Pb3 ^ xm);
            #pragma unroll
            for (int q = 0; q < 4; q++) {
                mma_fp16(acc[0][2*q+0], a00, a02, a01, a03, b[4*q+0], b[4*q+1]);
                mma_fp16(acc[0][2*q+1], a00, a02, a01, a03, b[4*q+2], b[4*q+3]);
                mma_fp16(acc[1][2*q+0], a10, a12, a11, a13, b[4*q+0], b[4*q+1]);
                mma_fp16(acc[1][2*q+1], a10, a12, a11, a13, b[4*q+2], b[4*q+3]);
            }
        }
    }

    #pragma unroll
    for (int am = 0; am < 2; am++) {
        #pragma unroll
        for (int p = 0; p < 2; p++) {
            int row = m0 + warp_m * 32 + am * 16 + p * 8 + r4;
            #pragma unroll
            for (int an = 0; an < 8; an++) {
                int col = n0 + warp_n * 64 + an * 8 + cc * 2;
                if (col < N) {
                    float vx = acc[am][an][2 * p], vy = acc[am][an][2 * p + 1];
                    if (EPI == 0) {
                        float* cp = (float*)Cv + (size_t)blockIdx.z * czstride
                                  + (size_t)row * ldc + col;
                        *(float2*)cp = make_float2(vx, vy);
                    } else if (EPI == 1) {
                        float* cp = (float*)Cv + (size_t)row * ldc + col;
                        float2 o = *(float2*)cp;
                        *(float2*)cp = make_float2(vx + o.x, vy + o.y);
                    } else if (EPI == 2) {
                        float2 bb2 = *(const float2*)(bias + col);
                        __half* cp = (__half*)Cv + (size_t)row * ldc + col;
                        *(__half2*)cp = __floats2half2_rn(
                            softplusf(vx + bb2.x), softplusf(vy + bb2.y));
                    } else {  // EPI == 3
                        __half* cp = (__half*)Cv + (size_t)row * ldc + col;
                        *(__half2*)cp = __floats2half2_rn(vx, vy);
                    }
                }
            }
        }
    }
    #undef ISSUE_CHUNK
}

// ---------------- split-K combine (4 f32 partials -> fp16 out) ------------
__global__ void combine4_kernel(const float* __restrict__ part,
                                __half* __restrict__ out, int n) {
    int i = blockIdx.x * 256 + threadIdx.x;
    if (i < n) {
        float s = part[i] + part[(size_t)n + i] + part[2 * (size_t)n + i]
                + part[3 * (size_t)n + i];
        out[i] = __float2half_rn(s);
    }
}

// ---------------- Embedding gather ----------------
__global__ void gather_kernel(const int* __restrict__ ids,
                              const float* __restrict__ embed,
                              float* __restrict__ h) {
    int t = blockIdx.x;
    int c = threadIdx.x;
    int id = ids[t];
    const float4* src = (const float4*)(embed + (size_t)id * D_MODEL);
    float4* dst = (float4*)(h + (size_t)t * D_MODEL);
    dst[c] = src[c];
}

// ---------------- RMSNorm (192 threads, float4); 0 = f32 out, 1 = fp16 ---
__global__ void rmsnorm_kernel(const float* __restrict__ x, long in_stride,
                               const float* __restrict__ w,
                               void* __restrict__ yv, long out_stride,
                               int half_out) {
    long r = blockIdx.x;
    const float* xr = x + r * in_stride;
    int tid = threadIdx.x; // 192
    float4 v = ((const float4*)xr)[tid];
    float s = v.x * v.x + v.y * v.y + v.z * v.z + v.w * v.w;
    #pragma unroll
    for (int o = 16; o; o >>= 1) s += __shfl_xor_sync(0xffffffffu, s, o);
    __shared__ float ws[6];
    __shared__ float sc;
    if ((tid & 31) == 0) ws[tid >> 5] = s;
    __syncthreads();
    if (tid == 0) {
        float tsum = 0.f;
        #pragma unroll
        for (int k = 0; k < 6; k++) tsum += ws[k];
        sc = rsqrtf(tsum * (1.0f / D_MODEL) + EPS);
    }
    __syncthreads();
    float scale = sc;
    float4 wv = ((const float4*)w)[tid];
    float o0 = v.x * scale * wv.x;
    float o1 = v.y * scale * wv.y;
    float o2 = v.z * scale * wv.z;
    float o3 = v.w * scale * wv.w;
    if (half_out) {
        __half2* yr = (__half2*)((__half*)yv + r * out_stride);
        yr[2 * tid]     = __floats2half2_rn(o0, o1);
        yr[2 * tid + 1] = __floats2half2_rn(o2, o3);
    } else {
        float4* yr = (float4*)((float*)yv + r * out_stride);
        yr[tid] = make_float4(o0, o1, o2, o3);
    }
}

// ---------------- Depthwise causal conv + bias + SiLU (half2, 2ch x 4t) ---
__global__ void conv_silu_kernel(const __half* __restrict__ proj,
                                 const float* __restrict__ cw,
                                 const float* __restrict__ cb,
                                 __half* __restrict__ ut) {
    long idx = (long)blockIdx.x * 256 + threadIdx.x;
    if (idx >= (long)(T_TOT / 4) * (I_INNER / 2)) return;
    int i2 = (int)(idx % (I_INNER / 2));
    long tq = idx / (I_INNER / 2);
    long t0 = tq * 4;
    int tl0 = (int)(t0 & (SEQ - 1));
    const __half2* p2 = (const __half2*)proj;
    const long S2 = I_INNER;
    long base = t0 * S2 + i2;

    float4 wa = ((const float4*)cw)[2 * i2];
    float4 wb = ((const float4*)cw)[2 * i2 + 1];
    float2 bia = ((const float2*)cb)[i2];

    float2 v[7];
    if (tl0 == 0) {
        v[0] = make_float2(0.f, 0.f); v[1] = v[0]; v[2] = v[0];
    } else {
        v[0] = __half22float2(p2[base - 3 * S2]);
        v[1] = __half22float2(p2[base - 2 * S2]);
        v[2] = __half22float2(p2[base - 1 * S2]);
    }
    v[3] = __half22float2(p2[base]);
    v[4] = __half22float2(p2[base + 1 * S2]);
    v[5] = __half22float2(p2[base + 2 * S2]);
    v[6] = __half22float2(p2[base + 3 * S2]);

    __half2* up = (__half2*)ut + t0 * (I_INNER / 2) + i2;
    #pragma unroll
    for (int k = 0; k < 4; k++) {
        float sa = bia.x, sb = bia.y;
        sa = fmaf(wa.x, v[k].x, sa);     sb = fmaf(wb.x, v[k].y, sb);
        sa = fmaf(wa.y, v[k + 1].x, sa); sb = fmaf(wb.y, v[k + 1].y, sb);
        sa = fmaf(wa.z, v[k + 2].x, sa); sb = fmaf(wb.z, v[k + 2].y, sb);
        sa = fmaf(wa.w, v[k + 3].x, sa); sb = fmaf(wb.w, v[k + 3].y, sb);
        float siga = 1.f / (1.f + __expf(-sa));
        float sigb = 1.f / (1.f + __expf(-sb));
        up[(size_t)k * (I_INNER / 2)] = __floats2half2_rn(sa * siga, sb * sigb);
    }
}

// ================= Chunked selective scan =================
__device__ __forceinline__ int a_is_arith(const float* A) {
    int ok = 1;
    #pragma unroll
    for (int n = 1; n < N_STATE; n++) {
        float ref = (float)(n + 1) * A[0];
        ok &= (fabsf(A[n] - ref) <= 1e-4f * fabsf(ref));
    }
    return ok;
}

__global__ __launch_bounds__(128)
void scan_phase1(const __half* __restrict__ dt,
                 const __half* __restrict__ ut,
                 const __half* __restrict__ xdbl,
                 const float* __restrict__ A_log,
                 float* __restrict__ pA_out,
                 float* __restrict__ hf_out) {
    int i = blockIdx.x * 128 + threadIdx.x;
    int c = blockIdx.y;
    int b = blockIdx.z;
    float A[N_STATE], h[N_STATE], pA[N_STATE];
    #pragma unroll
    for (int n = 0; n < N_STATE; n++) {
        A[n] = -__expf(A_log[i * N_STATE + n]);
        h[n] = 0.f; pA[n] = 1.f;
    }
    const int fast = a_is_arith(A);
    const float A0 = A[0];
    int t0 = c * CH_LEN;
    const __half* dtp = dt + (size_t)(b * SEQ + t0) * I_INNER + i;
    const __half* up  = ut + (size_t)(b * SEQ + t0) * I_INNER + i;
    const __half* xp  = xdbl + (size_t)(b * SEQ + t0) * 80;
    if (fast) {
        for (int t = 0; t < CH_LEN; t += 2) {
            float d0 = __half2float(dtp[(size_t)t * I_INNER]);
            float u0 = __half2float(up[(size_t)t * I_INNER]);
            float d1 = __half2float(dtp[(size_t)(t + 1) * I_INNER]);
            float u1 = __half2float(up[(size_t)(t + 1) * I_INNER]);
            float du0 = d0 * u0, du1 = d1 * u1;
            const __half2* xr0 = (const __half2*)(xp + (size_t)t * 80 + 48);
            const __half2* xr1 = (const __half2*)(xp + (size_t)(t + 1) * 80 + 48);
            float B0[N_STATE], B1[N_STATE];
            #pragma unroll
            for (int m = 0; m < 8; m++) {
                float2 b0 = __half22float2(xr0[m]);
                float2 b1 = __half22float2(xr1[m]);
                B0[2*m] = b0.x; B0[2*m+1] = b0.y;
                B1[2*m] = b1.x; B1[2*m+1] = b1.y;
            }
            float q0 = __expf(d0 * A0), q1 = __expf(d1 * A0);
            float c0 = 1.f, c1 = 1.f;
            #pragma unroll
            for (int n = 0; n < N_STATE; n++) {
                c0 *= q0; c1 *= q1;
                h[n] = fmaf(c0, h[n], du0 * B0[n]);
                h[n] = fmaf(c1, h[n], du1 * B1[n]);
                pA[n] *= c0 * c1;
            }
        }
    } else {
        for (int t = 0; t < CH_LEN; t++) {
            float d = __half2float(dtp[(size_t)t * I_INNER]);
            float u = __half2float(up[(size_t)t * I_INNER]);
            float du = d * u;
            const __half* xr = xp + (size_t)t * 80;
            #pragma unroll
            for (int n = 0; n < N_STATE; n++) {
                float Bn = __half2float(xr[48 + n]);
                float dA = __expf(d * A[n]);
                pA[n] *= dA;
                h[n] = fmaf(dA, h[n], du * Bn);
            }
        }
    }
    size_t off = (size_t)((b * NCHUNK + c) * I_INNER + i) * N_STATE;
    #pragma unroll
    for (int n = 0; n < N_STATE; n++) {
        pA_out[off + n] = pA[n];
        hf_out[off + n] = h[n];
    }
}

__global__ void scan_phase2(const float* __restrict__ pA,
                            const float* __restrict__ hf,
                            float* __restrict__ hin) {
    int ch = blockIdx.x * 128 + threadIdx.x;
    if (ch >= BATCH * I_INNER) return;
    int b = ch / I_INNER, i = ch % I_INNER;
    float h[N_STATE];
    #pragma unroll
    for (int n = 0; n < N_STATE; n++) h[n] = 0.f;
    for (int c = 0; c < NCHUNK; c++) {
        size_t off = (size_t)((b * NCHUNK + c) * I_INNER + i) * N_STATE;
        #pragma unroll
        for (int q = 0; q < 4; q++) {
            float4 p4 = *(const float4*)(pA + off + 4 * q);
            float4 f4 = *(const float4*)(hf + off + 4 * q);
            *(float4*)(hin + off + 4 * q) =
                make_float4(h[4*q], h[4*q+1], h[4*q+2], h[4*q+3]);
            h[4*q]   = fmaf(p4.x, h[4*q],   f4.x);
            h[4*q+1] = fmaf(p4.y, h[4*q+1], f4.y);
            h[4*q+2] = fmaf(p4.z, h[4*q+2], f4.z);
            h[4*q+3] = fmaf(p4.w, h[4*q+3], f4.w);
        }
    }
}

__global__ __launch_bounds__(128)
void scan_phase3(const __half* __restrict__ dt,
                 const __half* __restrict__ ut,
                 const __half* __restrict__ xdbl,
                 const float* __restrict__ A_log,
                 const float* __restrict__ Dp,
                 const __half* __restrict__ proj,
                 const float* __restrict__ hin,
                 __half* __restrict__ y) {
    int i = blockIdx.x * 128 + threadIdx.x;
    int c = blockIdx.y;
    int b = blockIdx.z;
    float A[N_STATE], h[N_STATE];
    size_t soff = (size_t)((b * NCHUNK + c) * I_INNER + i) * N_STATE;
    #pragma unroll
    for (int n = 0; n < N_STATE; n++) {
        A[n] = -__expf(A_log[i * N_STATE + n]);
        h[n] = hin[soff + n];
    }
    const int fast = a_is_arith(A);
    const float A0 = A[0];
    float Di = Dp[i];
    int t0 = c * CH_LEN;
    const __half* dtp = dt + (size_t)(b * SEQ + t0) * I_INNER + i;
    const __half* up  = ut + (size_t)(b * SEQ + t0) * I_INNER + i;
    const __half* gp  = proj + (size_t)(b * SEQ + t0) * 2 * I_INNER + I_INNER + i;
    const __half* xp  = xdbl + (size_t)(b * SEQ + t0) * 80;
    __half* yp        = y + (size_t)(b * SEQ + t0) * I_INNER + i;
    if (fast) {
        // t-unrolled x2 with batched half2 B/C loads (more MLP on the chain)
        for (int t = 0; t < CH_LEN; t += 2) {
            float d0 = __half2float(dtp[(size_t)t * I_INNER]);
            float u0 = __half2float(up[(size_t)t * I_INNER]);
            float g0 = __half2float(gp[(size_t)t * 2 * I_INNER]);
            float d1 = __half2float(dtp[(size_t)(t + 1) * I_INNER]);
            float u1 = __half2float(up[(size_t)(t + 1) * I_INNER]);
            float g1 = __half2float(gp[(size_t)(t + 1) * 2 * I_INNER]);
            float du0 = d0 * u0, du1 = d1 * u1;
            const __half2* xr0 = (const __half2*)(xp + (size_t)t * 80 + 48);
            const __half2* xr1 = (const __half2*)(xp + (size_t)(t + 1) * 80 + 48);
            float B0[N_STATE], C0[N_STATE], B1[N_STATE], C1[N_STATE];
            #pragma unroll
            for (int m = 0; m < 8; m++) {
                float2 bb0 = __half22float2(xr0[m]);
                float2 cc0 = __half22float2(xr0[8 + m]);
                float2 bb1 = __half22float2(xr1[m]);
                float2 cc1 = __half22float2(xr1[8 + m]);
                B0[2*m] = bb0.x; B0[2*m+1] = bb0.y;
                C0[2*m] = cc0.x; C0[2*m+1] = cc0.y;
                B1[2*m] = bb1.x; B1[2*m+1] = bb1.y;
                C1[2*m] = cc1.x; C1[2*m+1] = cc1.y;
            }
            float q0 = __expf(d0 * A0), q1 = __expf(d1 * A0);
            float c0 = 1.f, c1 = 1.f;
            float acc0 = 0.f, acc1 = 0.f;
            #pragma unroll
            for (int n = 0; n < N_STATE; n++) {
                c0 *= q0; c1 *= q1;
                h[n] = fmaf(c0, h[n], du0 * B0[n]);
                acc0 = fmaf(h[n], C0[n], acc0);
                h[n] = fmaf(c1, h[n], du1 * B1[n]);
                acc1 = fmaf(h[n], C1[n], acc1);
            }
            float sig0 = 1.f / (1.f + __expf(-g0));
            float sig1 = 1.f / (1.f + __expf(-g1));
            yp[(size_t)t * I_INNER] =
                __float2half_rn((acc0 + u0 * Di) * (g0 * sig0));
            yp[(size_t)(t + 1) * I_INNER] =
                __float2half_rn((acc1 + u1 * Di) * (g1 * sig1));
        }
    } else {
        for (int t = 0; t < CH_LEN; t++) {
            float d = __half2float(dtp[(size_t)t * I_INNER]);
            float u = __half2float(up[(size_t)t * I_INNER]);
            float du = d * u;
            const __half* xr = xp + (size_t)t * 80;
            float acc = 0.f;
            #pragma unroll
            for (int n = 0; n < N_STATE; n++) {
                float Bn = __half2float(xr[48 + n]);
                float Cx = __half2float(xr[64 + n]);
                float dA = __expf(d * A[n]);
                h[n] = fmaf(dA, h[n], du * Bn);
                acc = fmaf(h[n], Cx, acc);
            }
            float g = __half2float(gp[(size_t)t * 2 * I_INNER]);
            float sig = 1.f / (1.f + __expf(-g));
            yp[(size_t)t * I_INNER] = __float2half_rn((acc + u * Di) * (g * sig));
        }
    }
}

// ---------------- Logits: out[b,v] = dot(hn[b], embed[v]) ----------------
__global__ void logits_kernel(const float* __restrict__ hn,
                              const float* __restrict__ embed,
                              float* __restrict__ out) {
    __shared__ float sh[BATCH * D_MODEL];
    int tid = threadIdx.x; // 256
    for (int j = tid; j < BATCH * D_MODEL; j += 256) sh[j] = hn[j];
    __syncthreads();
    int warp = tid >> 5, lane = tid & 31;
    int v = blockIdx.x * 8 + warp;
    if (v >= VOCAB) return;
    const float* e = embed + (size_t)v * D_MODEL;
    float a0 = 0.f, a1 = 0.f, a2 = 0.f, a3 = 0.f;
    for (int j = lane; j < D_MODEL; j += 32) {
        float ev = e[j];
        a0 = fmaf(ev, sh[j], a0);
        a1 = fmaf(ev, sh[D_MODEL + j], a1);
        a2 = fmaf(ev, sh[2 * D_MODEL + j], a2);
        a3 = fmaf(ev, sh[3 * D_MODEL + j], a3);
    }
    #pragma unroll
    for (int o = 16; o; o >>= 1) {
        a0 += __shfl_down_sync(0xffffffffu, a0, o);
        a1 += __shfl_down_sync(0xffffffffu, a1, o);
        a2 += __shfl_down_sync(0xffffffffu, a2, o);
        a3 += __shfl_down_sync(0xffffffffu, a3, o);
    }
    if (lane == 0) {
        out[(size_t)0 * VOCAB + v] = a0;
        out[(size_t)1 * VOCAB + v] = a1;
        out[(size_t)2 * VOCAB + v] = a2;
        out[(size_t)3 * VOCAB + v] = a3;
    }
}

// ---------------- Launch ----------------
extern "C" void kernel_launch(void* const* d_in, const int* in_sizes, int n_in,
                              void* d_out, int out_size) {
    const int*   ids       = (const int*)  d_in[0];
    const float* embed     = (const float*)d_in[1];
    const float* norm_w    = (const float*)d_in[2];
    const float* in_proj_w = (const float*)d_in[3];
    const float* conv_w    = (const float*)d_in[4];
    const float* conv_b    = (const float*)d_in[5];
    const float* x_proj_w  = (const float*)d_in[6];
    const float* dt_proj_w = (const float*)d_in[7];
    const float* dt_proj_b = (const float*)d_in[8];
    const float* A_log     = (const float*)d_in[9];
    const float* D_param   = (const float*)d_in[10];
    const float* out_proj_w= (const float*)d_in[11];
    const float* norm_f_w  = (const float*)d_in[12];
    float* out = (float*)d_out;

    float *h, *hn, *pA, *hf, *hin, *xpart;
    __half *x, *proj, *ut, *xdbl, *dt, *y, *wh_in, *wh_x, *wh_dt, *wh_out;
    cudaGetSymbolAddress((void**)&h,     g_h);
    cudaGetSymbolAddress((void**)&x,     g_x);
    cudaGetSymbolAddress((void**)&proj,  g_proj);
    cudaGetSymbolAddress((void**)&ut,    g_ut);
    cudaGetSymbolAddress((void**)&xdbl,  g_xdbl);
    cudaGetSymbolAddress((void**)&dt,    g_dt);
    cudaGetSymbolAddress((void**)&y,     g_y);
    cudaGetSymbolAddress((void**)&hn,    g_hn);
    cudaGetSymbolAddress((void**)&pA,    g_pA);
    cudaGetSymbolAddress((void**)&hf,    g_hf);
    cudaGetSymbolAddress((void**)&hin,   g_hin);
    cudaGetSymbolAddress((void**)&xpart, g_xpart);
    cudaGetSymbolAddress((void**)&wh_in, g_wh_in);
    cudaGetSymbolAddress((void**)&wh_x,  g_wh_x);
    cudaGetSymbolAddress((void**)&wh_dt, g_wh_dt);
    cudaGetSymbolAddress((void**)&wh_out,g_wh_out);

    cudaFuncSetAttribute(tgemm<0>, cudaFuncAttributeMaxDynamicSharedMemorySize, TG_SMEM);
    cudaFuncSetAttribute(tgemm<1>, cudaFuncAttributeMaxDynamicSharedMemorySize, TG_SMEM);
    cudaFuncSetAttribute(tgemm<2>, cudaFuncAttributeMaxDynamicSharedMemorySize, TG_SMEM);
    cudaFuncSetAttribute(tgemm<3>, cudaFuncAttributeMaxDynamicSharedMemorySize, TG_SMEM);

    // weight conversions (all layers, one launch)
    {
        int n1 = L_LAYERS * 2 * I_INNER * D_MODEL;
        int n2 = L_LAYERS * 80 * I_INNER;
        int n3 = L_LAYERS * I_INNER * DT_RANK;
        int n4 = L_LAYERS * D_MODEL * I_INNER;
        f2h4_kernel<<<(n1 / 2 + 255) / 256, 256>>>(
            in_proj_w, wh_in, n1, x_proj_w, wh_x, n2,
            dt_proj_w, wh_dt, n3, out_proj_w, wh_out, n4);
    }

    gather_kernel<<<T_TOT, 192>>>(ids, embed, h);

    const int NXD = T_TOT * 80;

    for (int l = 0; l < L_LAYERS; l++) {
        rmsnorm_kernel<<<T_TOT, 192>>>(h, D_MODEL, norm_w + l * D_MODEL, x, D_MODEL, 1);

        // proj = x @ in_proj_w^T   (8192 x 3072 x 768), fp16 out
        tgemm<3><<<dim3(24, 64), 256, TG_SMEM>>>(
            x, D_MODEL, wh_in + (size_t)l * 2 * I_INNER * D_MODEL, D_MODEL,
            proj, 2 * I_INNER, 2 * I_INNER, D_MODEL, nullptr, D_MODEL, 0);

        conv_silu_kernel<<<((T_TOT / 4) * (I_INNER / 2) + 255) / 256, 256>>>(
            proj, conv_w + (size_t)l * I_INNER * K_CONV, conv_b + (size_t)l * I_INNER, ut);

        // xdbl = ut @ x_proj_w^T   (8192 x 80 x 1536), split-K x4 + combine
        tgemm<0><<<dim3(1, 64, 4), 256, TG_SMEM>>>(
            ut, I_INNER, wh_x + (size_t)l * 80 * I_INNER, I_INNER,
            xpart, 80, 80, I_INNER, nullptr, 384, (size_t)NXD);
        combine4_kernel<<<(NXD + 255) / 256, 256>>>(xpart, xdbl, NXD);

        // dt = softplus(dt_r @ dt_proj_w^T + b)   (8192 x 1536 x 48), fp16 out
        tgemm<2><<<dim3(12, 64), 256, TG_SMEM>>>(
            xdbl, 80, wh_dt + (size_t)l * I_INNER * DT_RANK, DT_RANK,
            dt, I_INNER, I_INNER, DT_RANK, dt_proj_b + (size_t)l * I_INNER,
            DT_RANK, 0);

        // chunked parallel scan
        const float* Al = A_log + (size_t)l * I_INNER * N_STATE;
        scan_phase1<<<dim3(I_INNER / 128, NCHUNK, BATCH), 128>>>(
            dt, ut, xdbl, Al, pA, hf);
        scan_phase2<<<(BATCH * I_INNER + 127) / 128, 128>>>(pA, hf, hin);
        scan_phase3<<<dim3(I_INNER / 128, NCHUNK, BATCH), 128>>>(
            dt, ut, xdbl, Al, D_param + (size_t)l * I_INNER, proj, hin, y);

        // h += y @ out_proj_w^T    (8192 x 768 x 1536)
        tgemm<1><<<dim3(6, 64), 256, TG_SMEM>>>(
            y, I_INNER, wh_out + (size_t)l * D_MODEL * I_INNER, I_INNER,
            h, D_MODEL, D_MODEL, I_INNER, nullptr, I_INNER, 0);
    }

    rmsnorm_kernel<<<BATCH, 192>>>(h + (size_t)(SEQ - 1) * D_MODEL,
                                   (long)SEQ * D_MODEL, norm_f_w, hn, D_MODEL, 0);
    logits_kernel<<<(VOCAB + 7) / 8, 256>>>(hn, embed, out);
}

// round 15
// speedup vs baseline: 1.7209x; 1.0343x over previous
#include <cuda_runtime.h>
#include <cuda_fp16.h>
#include <math.h>
#include <stdint.h>

// ---------------- Problem constants ----------------
#define BATCH 4
#define SEQ   2048
#define T_TOT (BATCH*SEQ)      // 8192
#define D_MODEL 768
#define L_LAYERS 4
#define N_STATE 16
#define K_CONV  4
#define I_INNER 1536           // 2*D_MODEL
#define DT_RANK 48
#define VOCAB 32000
#define EPS 1e-5f

// chunked scan config
#define CH_LEN 128
#define NCHUNK (SEQ / CH_LEN)   // 16

// ---------------- Scratch (static device globals; no allocs) ----------------
__device__ float  g_h   [(size_t)T_TOT * D_MODEL];
__device__ __half g_x   [(size_t)T_TOT * D_MODEL];
__device__ __half g_proj[(size_t)T_TOT * 2 * I_INNER];
__device__ __half g_ut  [(size_t)T_TOT * I_INNER];
__device__ __half g_xdbl[(size_t)T_TOT * 80];
__device__ __half g_dt  [(size_t)T_TOT * I_INNER];
__device__ __half g_y   [(size_t)T_TOT * I_INNER];
__device__ float  g_hn  [BATCH * D_MODEL];
__device__ float  g_xpart[(size_t)4 * T_TOT * 80];
// fp16 weight copies (all layers)
__device__ __half g_wh_in [(size_t)L_LAYERS * 2 * I_INNER * D_MODEL];
__device__ __half g_wh_x  [(size_t)L_LAYERS * 80 * I_INNER];
__device__ __half g_wh_dt [(size_t)L_LAYERS * I_INNER * DT_RANK];
__device__ __half g_wh_out[(size_t)L_LAYERS * D_MODEL * I_INNER];
// chunked-scan state: layout [b][c][i][n]
__device__ float g_pA  [(size_t)BATCH * NCHUNK * I_INNER * N_STATE];
__device__ float g_hf  [(size_t)BATCH * NCHUNK * I_INNER * N_STATE];
__device__ float g_hin [(size_t)BATCH * NCHUNK * I_INNER * N_STATE];

// ---------------- small helpers ----------------
__device__ __forceinline__ uint32_t smem_u32(const void* p) {
    uint32_t a;
    asm("{ .reg .u64 t; cvta.to.shared.u64 t, %1; cvt.u32.u64 %0, t; }"
        : "=r"(a) : "l"(p));
    return a;
}
__device__ __forceinline__ void cp_async16(uint32_t dst, const void* src, int sz) {
    asm volatile("cp.async.cg.shared.global [%0], [%1], 16, %2;"
                 :: "r"(dst), "l"(src), "r"(sz) : "memory");
}
#define CP_COMMIT() asm volatile("cp.async.commit_group;" ::: "memory")
#define CP_WAIT1()  asm volatile("cp.async.wait_group 1;" ::: "memory")

__device__ __forceinline__ void mma_fp16(float* d, uint32_t a0, uint32_t a1,
                                         uint32_t a2, uint32_t a3,
                                         uint32_t b0, uint32_t b1) {
    asm volatile(
        "mma.sync.aligned.m16n8k16.row.col.f32.f16.f16.f32 "
        "{%0,%1,%2,%3}, {%4,%5,%6,%7}, {%8,%9}, {%0,%1,%2,%3};"
        : "+f"(d[0]), "+f"(d[1]), "+f"(d[2]), "+f"(d[3])
        : "r"(a0), "r"(a1), "r"(a2), "r"(a3), "r"(b0), "r"(b1));
}

__device__ __forceinline__ void ldsm_x4(uint32_t& r0, uint32_t& r1,
                                        uint32_t& r2, uint32_t& r3, uint32_t addr) {
    asm volatile("ldmatrix.sync.aligned.m8n8.x4.shared.b16 {%0,%1,%2,%3}, [%4];"
                 : "=r"(r0), "=r"(r1), "=r"(r2), "=r"(r3) : "r"(addr));
}

__device__ __forceinline__ float softplusf(float v) {
    return (v > 20.f) ? v : log1pf(__expf(v));
}

// ---------------- merged f32 -> fp16 weight conversion (one launch) -------
__global__ void f2h4_kernel(const float* __restrict__ s0, __half* __restrict__ d0, int n0,
                            const float* __restrict__ s1, __half* __restrict__ d1, int n1,
                            const float* __restrict__ s2, __half* __restrict__ d2, int n2,
                            const float* __restrict__ s3, __half* __restrict__ d3, int n3) {
    int i = blockIdx.x * 256 + threadIdx.x;
    int stride = gridDim.x * 256;
    for (int j = i; j < n0 / 2; j += stride) {
        float2 v = ((const float2*)s0)[j];
        ((__half2*)d0)[j] = __floats2half2_rn(v.x, v.y);
    }
    for (int j = i; j < n1 / 2; j += stride) {
        float2 v = ((const float2*)s1)[j];
        ((__half2*)d1)[j] = __floats2half2_rn(v.x, v.y);
    }
    for (int j = i; j < n2 / 2; j += stride) {
        float2 v = ((const float2*)s2)[j];
        ((__half2*)d2)[j] = __floats2half2_rn(v.x, v.y);
    }
    for (int j = i; j < n3 / 2; j += stride) {
        float2 v = ((const float2*)s3)[j];
        ((__half2*)d3)[j] = __floats2half2_rn(v.x, v.y);
    }
}

// ================= tensor-core fp16 GEMM (R12 config: 128x128, 8 warps) =====
// C[m,n] = sum_k A[m,k]*B[n,k].  A: 8192 x K rm fp16, B: N x K rm fp16.
// CTA tile 128x128, 8 warps (4m x 2n), warp tile 32x64, K chunks of 64 halves,
// 3-stage cp.async pipeline w/ single sync, XOR-swizzled smem, batched ldsm.
// 2 CTAs/SM (hard requirement: sync bubbles need a co-resident CTA).
// EPI: 0 = store f32 (+splitK z-offset), 1 = f32 +=, 2 = softplus->fp16,
//      3 = store fp16.
#define TG_SMEM (6 * 16384)

template<int EPI>
__global__ __launch_bounds__(256, 2)
void tgemm(const __half* __restrict__ A, int lda,
           const __half* __restrict__ B, int ldb,
           void* __restrict__ Cv, int ldc,
           int N, int K, const float* __restrict__ bias,
           int Kper, size_t czstride) {
    extern __shared__ char smem[];
    const uint32_t sbA = smem_u32(smem);
    const uint32_t sbB = sbA + 3 * 16384;

    const int tid = threadIdx.x;
    const int wid = tid >> 5, lane = tid & 31;
    const int warp_m = wid >> 1, warp_n = wid & 1;
    const int r4 = lane >> 2, cc = lane & 3;
    const int m0 = blockIdx.y * 128, n0 = blockIdx.x * 128;
    const int Nvalid = (N - n0 < 128) ? (N - n0) : 128;

    const int koff = blockIdx.z * Kper;
    int Kloc = K - koff; if (Kloc > Kper) Kloc = Kper;
    const __half* Arow = A + (size_t)m0 * lda + koff;
    const __half* Brow = B + (size_t)n0 * ldb + koff;

    const int nc = (Kloc + 63) / 64;

    float acc[2][8][4];
    #pragma unroll
    for (int i = 0; i < 2; i++)
        #pragma unroll
        for (int j = 0; j < 8; j++)
            #pragma unroll
            for (int v = 0; v < 4; v++) acc[i][j][v] = 0.f;

    const int crow = tid >> 1;
    const int gb = (tid & 1) * 4;
    const bool bvalid = crow < Nvalid;
    const uint32_t swbase = (uint32_t)crow * 128;

    const int lrow8 = ((lane & 16) >> 1) + (lane & 7);
    const int gsel  = (lane >> 3) & 1;
    uint32_t aoff[2], boff[4];
    #pragma unroll
    for (int am = 0; am < 2; am++) {
        int row = warp_m * 32 + am * 16 + lrow8;
        aoff[am] = (uint32_t)row * 128 + ((uint32_t)((row & 7) ^ gsel) << 4);
    }
    #pragma unroll
    for (int nb = 0; nb < 4; nb++) {
        int row = warp_n * 64 + nb * 16 + lrow8;
        boff[nb] = (uint32_t)row * 128 + ((uint32_t)((row & 7) ^ gsel) << 4);
    }

    #define ISSUE_CHUNK(ch) do {                                            \
        int _st = (ch) % 3;                                                 \
        uint32_t _ab = sbA + _st * 16384;                                   \
        uint32_t _bb = sbB + _st * 16384;                                   \
        int _k0c = (ch) * 64;                                               \
        _Pragma("unroll")                                                   \
        for (int _j = 0; _j < 4; _j++) {                                    \
            int _g = gb + _j;                                               \
            int _k0 = _k0c + _g * 8;                                        \
            int _sz = (Kloc - _k0) * 2;                                     \
            _sz = _sz < 0 ? 0 : (_sz > 16 ? 16 : _sz);                      \
            uint32_t _sw = swbase + ((uint32_t)(_g ^ (crow & 7)) << 4);     \
            const __half* _sa = Arow + (size_t)crow * lda + (_sz ? _k0 : 0); \
            cp_async16(_ab + _sw, _sa, _sz);                                \
            int _szb = bvalid ? _sz : 0;                                    \
            const __half* _sb = Brow + (_szb ? ((size_t)crow * ldb + _k0) : 0); \
            cp_async16(_bb + _sw, _sb, _szb);                               \
        }                                                                   \
    } while (0)

    ISSUE_CHUNK(0);
    CP_COMMIT();
    if (nc > 1) ISSUE_CHUNK(1);
    CP_COMMIT();

    for (int c = 0; c < nc; c++) {
        CP_WAIT1();
        __syncthreads();
        if (c + 2 < nc) ISSUE_CHUNK(c + 2);
        CP_COMMIT();

        const uint32_t pa = sbA + (c % 3) * 16384;
        const uint32_t pb = sbB + (c % 3) * 16384;
        const uint32_t Pa0 = pa + aoff[0], Pa1 = pa + aoff[1];
        const uint32_t Pb0 = pb + boff[0], Pb1 = pb + boff[1];
        const uint32_t Pb2 = pb + boff[2], Pb3 = pb + boff[3];

        #pragma unroll
        for (int ks = 0; ks < 4; ks++) {
            const uint32_t xm = (uint32_t)ks << 5;
            uint32_t a00, a01, a02, a03, a10, a11, a12, a13;
            uint32_t b[16];
            ldsm_x4(a00, a01, a02, a03, Pa0 ^ xm);
            ldsm_x4(a10, a11, a12, a13, Pa1 ^ xm);
            ldsm_x4(b[0],  b[1],  b[2],  b[3],  Pb0 ^ xm);
            ldsm_x4(b[4],  b[5],  b[6],  b[7],  Pb1 ^ xm);
            ldsm_x4(b[8],  b[9],  b[10], b[11], Pb2 ^ xm);
            ldsm_x4(b[12], b[13], b[14], b[15], Pb3 ^ xm);
            #pragma unroll
            for (int q = 0; q < 4; q++) {
                mma_fp16(acc[0][2*q+0], a00, a02, a01, a03, b[4*q+0], b[4*q+1]);
                mma_fp16(acc[0][2*q+1], a00, a02, a01, a03, b[4*q+2], b[4*q+3]);
                mma_fp16(acc[1][2*q+0], a10, a12, a11, a13, b[4*q+0], b[4*q+1]);
                mma_fp16(acc[1][2*q+1], a10, a12, a11, a13, b[4*q+2], b[4*q+3]);
            }
        }
    }

    #pragma unroll
    for (int am = 0; am < 2; am++) {
        #pragma unroll
        for (int p = 0; p < 2; p++) {
            int row = m0 + warp_m * 32 + am * 16 + p * 8 + r4;
            #pragma unroll
            for (int an = 0; an < 8; an++) {
                int col = n0 + warp_n * 64 + an * 8 + cc * 2;
                if (col < N) {
                    float vx = acc[am][an][2 * p], vy = acc[am][an][2 * p + 1];
                    if (EPI == 0) {
                        float* cp = (float*)Cv + (size_t)blockIdx.z * czstride
                                  + (size_t)row * ldc + col;
                        *(float2*)cp = make_float2(vx, vy);
                    } else if (EPI == 1) {
                        float* cp = (float*)Cv + (size_t)row * ldc + col;
                        float2 o = *(float2*)cp;
                        *(float2*)cp = make_float2(vx + o.x, vy + o.y);
                    } else if (EPI == 2) {
                        float2 bb2 = *(const float2*)(bias + col);
                        __half* cp = (__half*)Cv + (size_t)row * ldc + col;
                        *(__half2*)cp = __floats2half2_rn(
                            softplusf(vx + bb2.x), softplusf(vy + bb2.y));
                    } else {  // EPI == 3
                        __half* cp = (__half*)Cv + (size_t)row * ldc + col;
                        *(__half2*)cp = __floats2half2_rn(vx, vy);
                    }
                }
            }
        }
    }
    #undef ISSUE_CHUNK
}

// ---------------- split-K combine (4 f32 partials -> fp16 out) ------------
__global__ void combine4_kernel(const float* __restrict__ part,
                                __half* __restrict__ out, int n) {
    int i = blockIdx.x * 256 + threadIdx.x;
    if (i < n) {
        float s = part[i] + part[(size_t)n + i] + part[2 * (size_t)n + i]
                + part[3 * (size_t)n + i];
        out[i] = __float2half_rn(s);
    }
}

// ---------------- Embedding gather ----------------
__global__ void gather_kernel(const int* __restrict__ ids,
                              const float* __restrict__ embed,
                              float* __restrict__ h) {
    int t = blockIdx.x;
    int c = threadIdx.x;
    int id = ids[t];
    const float4* src = (const float4*)(embed + (size_t)id * D_MODEL);
    float4* dst = (float4*)(h + (size_t)t * D_MODEL);
    dst[c] = src[c];
}

// ---------------- RMSNorm (192 threads, float4); 0 = f32 out, 1 = fp16 ---
__global__ void rmsnorm_kernel(const float* __restrict__ x, long in_stride,
                               const float* __restrict__ w,
                               void* __restrict__ yv, long out_stride,
                               int half_out) {
    long r = blockIdx.x;
    const float* xr = x + r * in_stride;
    int tid = threadIdx.x; // 192
    float4 v = ((const float4*)xr)[tid];
    float s = v.x * v.x + v.y * v.y + v.z * v.z + v.w * v.w;
    #pragma unroll
    for (int o = 16; o; o >>= 1) s += __shfl_xor_sync(0xffffffffu, s, o);
    __shared__ float ws[6];
    __shared__ float sc;
    if ((tid & 31) == 0) ws[tid >> 5] = s;
    __syncthreads();
    if (tid == 0) {
        float tsum = 0.f;
        #pragma unroll
        for (int k = 0; k < 6; k++) tsum += ws[k];
        sc = rsqrtf(tsum * (1.0f / D_MODEL) + EPS);
    }
    __syncthreads();
    float scale = sc;
    float4 wv = ((const float4*)w)[tid];
    float o0 = v.x * scale * wv.x;
    float o1 = v.y * scale * wv.y;
    float o2 = v.z * scale * wv.z;
    float o3 = v.w * scale * wv.w;
    if (half_out) {
        __half2* yr = (__half2*)((__half*)yv + r * out_stride);
        yr[2 * tid]     = __floats2half2_rn(o0, o1);
        yr[2 * tid + 1] = __floats2half2_rn(o2, o3);
    } else {
        float4* yr = (float4*)((float*)yv + r * out_stride);
        yr[tid] = make_float4(o0, o1, o2, o3);
    }
}

// ---------------- Depthwise causal conv + bias + SiLU (half2, 2ch x 4t) ---
__global__ void conv_silu_kernel(const __half* __restrict__ proj,
                                 const float* __restrict__ cw,
                                 const float* __restrict__ cb,
                                 __half* __restrict__ ut) {
    long idx = (long)blockIdx.x * 256 + threadIdx.x;
    if (idx >= (long)(T_TOT / 4) * (I_INNER / 2)) return;
    int i2 = (int)(idx % (I_INNER / 2));
    long tq = idx / (I_INNER / 2);
    long t0 = tq * 4;
    int tl0 = (int)(t0 & (SEQ - 1));
    const __half2* p2 = (const __half2*)proj;
    const long S2 = I_INNER;
    long base = t0 * S2 + i2;

    float4 wa = ((const float4*)cw)[2 * i2];
    float4 wb = ((const float4*)cw)[2 * i2 + 1];
    float2 bia = ((const float2*)cb)[i2];

    float2 v[7];
    if (tl0 == 0) {
        v[0] = make_float2(0.f, 0.f); v[1] = v[0]; v[2] = v[0];
    } else {
        v[0] = __half22float2(p2[base - 3 * S2]);
        v[1] = __half22float2(p2[base - 2 * S2]);
        v[2] = __half22float2(p2[base - 1 * S2]);
    }
    v[3] = __half22float2(p2[base]);
    v[4] = __half22float2(p2[base + 1 * S2]);
    v[5] = __half22float2(p2[base + 2 * S2]);
    v[6] = __half22float2(p2[base + 3 * S2]);

    __half2* up = (__half2*)ut + t0 * (I_INNER / 2) + i2;
    #pragma unroll
    for (int k = 0; k < 4; k++) {
        float sa = bia.x, sb = bia.y;
        sa = fmaf(wa.x, v[k].x, sa);     sb = fmaf(wb.x, v[k].y, sb);
        sa = fmaf(wa.y, v[k + 1].x, sa); sb = fmaf(wb.y, v[k + 1].y, sb);
        sa = fmaf(wa.z, v[k + 2].x, sa); sb = fmaf(wb.z, v[k + 2].y, sb);
        sa = fmaf(wa.w, v[k + 3].x, sa); sb = fmaf(wb.w, v[k + 3].y, sb);
        float siga = 1.f / (1.f + __expf(-sa));
        float sigb = 1.f / (1.f + __expf(-sb));
        up[(size_t)k * (I_INNER / 2)] = __floats2half2_rn(sa * siga, sb * sigb);
    }
}

// ================= Chunked selective scan =================
__device__ __forceinline__ int a_is_arith(const float* A) {
    int ok = 1;
    #pragma unroll
    for (int n = 1; n < N_STATE; n++) {
        float ref = (float)(n + 1) * A[0];
        ok &= (fabsf(A[n] - ref) <= 1e-4f * fabsf(ref));
    }
    return ok;
}

__global__ __launch_bounds__(128)
void scan_phase1(const __half* __restrict__ dt,
                 const __half* __restrict__ ut,
                 const __half* __restrict__ xdbl,
                 const float* __restrict__ A_log,
                 float* __restrict__ pA_out,
                 float* __restrict__ hf_out) {
    int i = blockIdx.x * 128 + threadIdx.x;
    int c = blockIdx.y;
    int b = blockIdx.z;
    float A[N_STATE], h[N_STATE], pA[N_STATE];
    #pragma unroll
    for (int n = 0; n < N_STATE; n++) {
        A[n] = -__expf(A_log[i * N_STATE + n]);
        h[n] = 0.f; pA[n] = 1.f;
    }
    const int fast = a_is_arith(A);
    const float A0 = A[0];
    int t0 = c * CH_LEN;
    const __half* dtp = dt + (size_t)(b * SEQ + t0) * I_INNER + i;
    const __half* up  = ut + (size_t)(b * SEQ + t0) * I_INNER + i;
    const __half* xp  = xdbl + (size_t)(b * SEQ + t0) * 80;
    if (fast) {
        for (int t = 0; t < CH_LEN; t += 2) {
            float d0 = __half2float(dtp[(size_t)t * I_INNER]);
            float u0 = __half2float(up[(size_t)t * I_INNER]);
            float d1 = __half2float(dtp[(size_t)(t + 1) * I_INNER]);
            float u1 = __half2float(up[(size_t)(t + 1) * I_INNER]);
            float du0 = d0 * u0, du1 = d1 * u1;
            const __half2* xr0 = (const __half2*)(xp + (size_t)t * 80 + 48);
            const __half2* xr1 = (const __half2*)(xp + (size_t)(t + 1) * 80 + 48);
            float B0[N_STATE], B1[N_STATE];
            #pragma unroll
            for (int m = 0; m < 8; m++) {
                float2 b0 = __half22float2(xr0[m]);
                float2 b1 = __half22float2(xr1[m]);
                B0[2*m] = b0.x; B0[2*m+1] = b0.y;
                B1[2*m] = b1.x; B1[2*m+1] = b1.y;
            }
            float q0 = __expf(d0 * A0), q1 = __expf(d1 * A0);
            float c0 = 1.f, c1 = 1.f;
            #pragma unroll
            for (int n = 0; n < N_STATE; n++) {
                c0 *= q0; c1 *= q1;
                h[n] = fmaf(c0, h[n], du0 * B0[n]);
                h[n] = fmaf(c1, h[n], du1 * B1[n]);
                pA[n] *= c0 * c1;
            }
        }
    } else {
        for (int t = 0; t < CH_LEN; t++) {
            float d = __half2float(dtp[(size_t)t * I_INNER]);
            float u = __half2float(up[(size_t)t * I_INNER]);
            float du = d * u;
            const __half* xr = xp + (size_t)t * 80;
            #pragma unroll
            for (int n = 0; n < N_STATE; n++) {
                float Bn = __half2float(xr[48 + n]);
                float dA = __expf(d * A[n]);
                pA[n] *= dA;
                h[n] = fmaf(dA, h[n], du * Bn);
            }
        }
    }
    size_t off = (size_t)((b * NCHUNK + c) * I_INNER + i) * N_STATE;
    #pragma unroll
    for (int n = 0; n < N_STATE; n++) {
        pA_out[off + n] = pA[n];
        hf_out[off + n] = h[n];
    }
}

__global__ void scan_phase2(const float* __restrict__ pA,
                            const float* __restrict__ hf,
                            float* __restrict__ hin) {
    int ch = blockIdx.x * 64 + threadIdx.x;
    if (ch >= BATCH * I_INNER) return;
    int b = ch / I_INNER, i = ch % I_INNER;
    float h[N_STATE];
    #pragma unroll
    for (int n = 0; n < N_STATE; n++) h[n] = 0.f;
    for (int c = 0; c < NCHUNK; c++) {
        size_t off = (size_t)((b * NCHUNK + c) * I_INNER + i) * N_STATE;
        #pragma unroll
        for (int q = 0; q < 4; q++) {
            float4 p4 = *(const float4*)(pA + off + 4 * q);
            float4 f4 = *(const float4*)(hf + off + 4 * q);
            *(float4*)(hin + off + 4 * q) =
                make_float4(h[4*q], h[4*q+1], h[4*q+2], h[4*q+3]);
            h[4*q]   = fmaf(p4.x, h[4*q],   f4.x);
            h[4*q+1] = fmaf(p4.y, h[4*q+1], f4.y);
            h[4*q+2] = fmaf(p4.z, h[4*q+2], f4.z);
            h[4*q+3] = fmaf(p4.w, h[4*q+3], f4.w);
        }
    }
}

__global__ __launch_bounds__(128)
void scan_phase3(const __half* __restrict__ dt,
                 const __half* __restrict__ ut,
                 const __half* __restrict__ xdbl,
                 const float* __restrict__ A_log,
                 const float* __restrict__ Dp,
                 const __half* __restrict__ proj,
                 const float* __restrict__ hin,
                 __half* __restrict__ y) {
    int i = blockIdx.x * 128 + threadIdx.x;
    int c = blockIdx.y;
    int b = blockIdx.z;
    float A[N_STATE], h[N_STATE];
    size_t soff = (size_t)((b * NCHUNK + c) * I_INNER + i) * N_STATE;
    #pragma unroll
    for (int n = 0; n < N_STATE; n++) {
        A[n] = -__expf(A_log[i * N_STATE + n]);
        h[n] = hin[soff + n];
    }
    const int fast = a_is_arith(A);
    const float A0 = A[0];
    float Di = Dp[i];
    int t0 = c * CH_LEN;
    const __half* dtp = dt + (size_t)(b * SEQ + t0) * I_INNER + i;
    const __half* up  = ut + (size_t)(b * SEQ + t0) * I_INNER + i;
    const __half* gp  = proj + (size_t)(b * SEQ + t0) * 2 * I_INNER + I_INNER + i;
    const __half* xp  = xdbl + (size_t)(b * SEQ + t0) * 80;
    __half* yp        = y + (size_t)(b * SEQ + t0) * I_INNER + i;
    if (fast) {
        for (int t = 0; t < CH_LEN; t++) {
            float d = __half2float(dtp[(size_t)t * I_INNER]);
            float u = __half2float(up[(size_t)t * I_INNER]);
            float g = __half2float(gp[(size_t)t * 2 * I_INNER]);
            float du = d * u;
            const __half2* xr2 = (const __half2*)(xp + (size_t)t * 80 + 48);
            float Bn[N_STATE], Cn[N_STATE];
            #pragma unroll
            for (int m = 0; m < 8; m++) {
                float2 bb = __half22float2(xr2[m]);
                float2 cx = __half22float2(xr2[8 + m]);
                Bn[2*m] = bb.x; Bn[2*m+1] = bb.y;
                Cn[2*m] = cx.x; Cn[2*m+1] = cx.y;
            }
            float q = __expf(d * A0);
            float dAc = 1.f;
            float acc = 0.f;
            #pragma unroll
            for (int n = 0; n < N_STATE; n++) {
                dAc *= q;
                h[n] = fmaf(dAc, h[n], du * Bn[n]);
                acc = fmaf(h[n], Cn[n], acc);
            }
            float sig = 1.f / (1.f + __expf(-g));
            yp[(size_t)t * I_INNER] = __float2half_rn((acc + u * Di) * (g * sig));
        }
    } else {
        for (int t = 0; t < CH_LEN; t++) {
            float d = __half2float(dtp[(size_t)t * I_INNER]);
            float u = __half2float(up[(size_t)t * I_INNER]);
            float du = d * u;
            const __half* xr = xp + (size_t)t * 80;
            float acc = 0.f;
            #pragma unroll
            for (int n = 0; n < N_STATE; n++) {
                float Bn = __half2float(xr[48 + n]);
                float Cx = __half2float(xr[64 + n]);
                float dA = __expf(d * A[n]);
                h[n] = fmaf(dA, h[n], du * Bn);
                acc = fmaf(h[n], Cx, acc);
            }
            float g = __half2float(gp[(size_t)t * 2 * I_INNER]);
            float sig = 1.f / (1.f + __expf(-g));
            yp[(size_t)t * I_INNER] = __float2half_rn((acc + u * Di) * (g * sig));
        }
    }
}

// ---------------- Logits: out[b,v] = dot(hn[b], embed[v]) ----------------
__global__ void logits_kernel(const float* __restrict__ hn,
                              const float* __restrict__ embed,
                              float* __restrict__ out) {
    __shared__ float sh[BATCH * D_MODEL];
    int tid = threadIdx.x; // 256
    for (int j = tid; j < BATCH * D_MODEL; j += 256) sh[j] = hn[j];
    __syncthreads();
    int warp = tid >> 5, lane = tid & 31;
    int v = blockIdx.x * 8 + warp;
    if (v >= VOCAB) return;
    const float* e = embed + (size_t)v * D_MODEL;
    float a0 = 0.f, a1 = 0.f, a2 = 0.f, a3 = 0.f;
    for (int j = lane; j < D_MODEL; j += 32) {
        float ev = e[j];
        a0 = fmaf(ev, sh[j], a0);
        a1 = fmaf(ev, sh[D_MODEL + j], a1);
        a2 = fmaf(ev, sh[2 * D_MODEL + j], a2);
        a3 = fmaf(ev, sh[3 * D_MODEL + j], a3);
    }
    #pragma unroll
    for (int o = 16; o; o >>= 1) {
        a0 += __shfl_down_sync(0xffffffffu, a0, o);
        a1 += __shfl_down_sync(0xffffffffu, a1, o);
        a2 += __shfl_down_sync(0xffffffffu, a2, o);
        a3 += __shfl_down_sync(0xffffffffu, a3, o);
    }
    if (lane == 0) {
        out[(size_t)0 * VOCAB + v] = a0;
        out[(size_t)1 * VOCAB + v] = a1;
        out[(size_t)2 * VOCAB + v] = a2;
        out[(size_t)3 * VOCAB + v] = a3;
    }
}

// ---------------- Launch ----------------
extern "C" void kernel_launch(void* const* d_in, const int* in_sizes, int n_in,
                              void* d_out, int out_size) {
    const int*   ids       = (const int*)  d_in[0];
    const float* embed     = (const float*)d_in[1];
    const float* norm_w    = (const float*)d_in[2];
    const float* in_proj_w = (const float*)d_in[3];
    const float* conv_w    = (const float*)d_in[4];
    const float* conv_b    = (const float*)d_in[5];
    const float* x_proj_w  = (const float*)d_in[6];
    const float* dt_proj_w = (const float*)d_in[7];
    const float* dt_proj_b = (const float*)d_in[8];
    const float* A_log     = (const float*)d_in[9];
    const float* D_param   = (const float*)d_in[10];
    const float* out_proj_w= (const float*)d_in[11];
    const float* norm_f_w  = (const float*)d_in[12];
    float* out = (float*)d_out;

    float *h, *hn, *pA, *hf, *hin, *xpart;
    __half *x, *proj, *ut, *xdbl, *dt, *y, *wh_in, *wh_x, *wh_dt, *wh_out;
    cudaGetSymbolAddress((void**)&h,     g_h);
    cudaGetSymbolAddress((void**)&x,     g_x);
    cudaGetSymbolAddress((void**)&proj,  g_proj);
    cudaGetSymbolAddress((void**)&ut,    g_ut);
    cudaGetSymbolAddress((void**)&xdbl,  g_xdbl);
    cudaGetSymbolAddress((void**)&dt,    g_dt);
    cudaGetSymbolAddress((void**)&y,     g_y);
    cudaGetSymbolAddress((void**)&hn,    g_hn);
    cudaGetSymbolAddress((void**)&pA,    g_pA);
    cudaGetSymbolAddress((void**)&hf,    g_hf);
    cudaGetSymbolAddress((void**)&hin,   g_hin);
    cudaGetSymbolAddress((void**)&xpart, g_xpart);
    cudaGetSymbolAddress((void**)&wh_in, g_wh_in);
    cudaGetSymbolAddress((void**)&wh_x,  g_wh_x);
    cudaGetSymbolAddress((void**)&wh_dt, g_wh_dt);
    cudaGetSymbolAddress((void**)&wh_out,g_wh_out);

    cudaFuncSetAttribute(tgemm<0>, cudaFuncAttributeMaxDynamicSharedMemorySize, TG_SMEM);
    cudaFuncSetAttribute(tgemm<1>, cudaFuncAttributeMaxDynamicSharedMemorySize, TG_SMEM);
    cudaFuncSetAttribute(tgemm<2>, cudaFuncAttributeMaxDynamicSharedMemorySize, TG_SMEM);
    cudaFuncSetAttribute(tgemm<3>, cudaFuncAttributeMaxDynamicSharedMemorySize, TG_SMEM);

    // weight conversions (all layers, one launch)
    {
        int n1 = L_LAYERS * 2 * I_INNER * D_MODEL;
        int n2 = L_LAYERS * 80 * I_INNER;
        int n3 = L_LAYERS * I_INNER * DT_RANK;
        int n4 = L_LAYERS * D_MODEL * I_INNER;
        f2h4_kernel<<<(n1 / 2 + 255) / 256, 256>>>(
            in_proj_w, wh_in, n1, x_proj_w, wh_x, n2,
            dt_proj_w, wh_dt, n3, out_proj_w, wh_out, n4);
    }

    gather_kernel<<<T_TOT, 192>>>(ids, embed, h);

    const int NXD = T_TOT * 80;

    for (int l = 0; l < L_LAYERS; l++) {
        rmsnorm_kernel<<<T_TOT, 192>>>(h, D_MODEL, norm_w + l * D_MODEL, x, D_MODEL, 1);

        // proj = x @ in_proj_w^T   (8192 x 3072 x 768), fp16 out
        tgemm<3><<<dim3(24, 64), 256, TG_SMEM>>>(
            x, D_MODEL, wh_in + (size_t)l * 2 * I_INNER * D_MODEL, D_MODEL,
            proj, 2 * I_INNER, 2 * I_INNER, D_MODEL, nullptr, D_MODEL, 0);

        conv_silu_kernel<<<((T_TOT / 4) * (I_INNER / 2) + 255) / 256, 256>>>(
            proj, conv_w + (size_t)l * I_INNER * K_CONV, conv_b + (size_t)l * I_INNER, ut);

        // xdbl = ut @ x_proj_w^T   (8192 x 80 x 1536), split-K x4 + combine
        tgemm<0><<<dim3(1, 64, 4), 256, TG_SMEM>>>(
            ut, I_INNER, wh_x + (size_t)l * 80 * I_INNER, I_INNER,
            xpart, 80, 80, I_INNER, nullptr, 384, (size_t)NXD);
        combine4_kernel<<<(NXD + 255) / 256, 256>>>(xpart, xdbl, NXD);

        // dt = softplus(dt_r @ dt_proj_w^T + b)   (8192 x 1536 x 48), fp16 out
        tgemm<2><<<dim3(12, 64), 256, TG_SMEM>>>(
            xdbl, 80, wh_dt + (size_t)l * I_INNER * DT_RANK, DT_RANK,
            dt, I_INNER, I_INNER, DT_RANK, dt_proj_b + (size_t)l * I_INNER,
            DT_RANK, 0);

        // chunked parallel scan
        const float* Al = A_log + (size_t)l * I_INNER * N_STATE;
        scan_phase1<<<dim3(I_INNER / 128, NCHUNK, BATCH), 128>>>(
            dt, ut, xdbl, Al, pA, hf);
        scan_phase2<<<(BATCH * I_INNER + 63) / 64, 64>>>(pA, hf, hin);
        scan_phase3<<<dim3(I_INNER / 128, NCHUNK, BATCH), 128>>>(
            dt, ut, xdbl, Al, D_param + (size_t)l * I_INNER, proj, hin, y);

        // h += y @ out_proj_w^T    (8192 x 768 x 1536)
        tgemm<1><<<dim3(6, 64), 256, TG_SMEM>>>(
            y, I_INNER, wh_out + (size_t)l * D_MODEL * I_INNER, I_INNER,
            h, D_MODEL, D_MODEL, I_INNER, nullptr, I_INNER, 0);
    }

    rmsnorm_kernel<<<BATCH, 192>>>(h + (size_t)(SEQ - 1) * D_MODEL,
                                   (long)SEQ * D_MODEL, norm_f_w, hn, D_MODEL, 0);
    logits_kernel<<<(VOCAB + 7) / 8, 256>>>(hn, embed, out);
}